// round 1
// baseline (speedup 1.0000x reference)
#include <cuda_runtime.h>
#include <math.h>

// ---------------------------------------------------------------------------
// RoPE Multi-Head Attention, fp32 baseline (SIMT, no tensor cores yet)
//   x:[2,2048,1024]  Wq/Wk/Wv/Wo:[1024,1024]  b*: [1024]
//   out = O-proj( softmax(rope(Q) rope(K)^T / 8) V )
// Pipeline:
//   1) gemm_bias<1>(x,Wq,bq -> Qh[B,H,T,Dh])   (head-transposed epilogue)
//   2) gemm_bias<1>(x,Wk,bk -> Kh), gemm_bias<1>(x,Wv,bv -> Vh)
//   3) rope_kernel: in-place pairwise rotate Qh,Kh
//   4) attn_kernel: flash-style streaming softmax -> attn[B,T,D]
//   5) gemm_bias<0>(attn,Wo,bo -> d_out[B,T,D])
// ---------------------------------------------------------------------------

namespace {
constexpr int Bn  = 2;
constexpr int Tn  = 2048;
constexpr int Hn  = 16;
constexpr int Dhn = 64;
constexpr int Dn  = 1024;          // Hn * Dhn
constexpr int Mn  = Bn * Tn;       // 4096 rows for the projections
}

// Scratch (static device arrays: no allocation anywhere)
__device__ float g_Qh[(size_t)Bn * Hn * Tn * Dhn];
__device__ float g_Kh[(size_t)Bn * Hn * Tn * Dhn];
__device__ float g_Vh[(size_t)Bn * Hn * Tn * Dhn];
__device__ float g_attn[(size_t)Bn * Tn * Dn];

// ---------------------------------------------------------------------------
// Tiled GEMM:  C[m,n] = sum_k A[m,k] * W[n,k] + bias[n]
//   A: [Mn,1024] row-major, W: [1024,1024] row-major (torch Linear weight)
//   MODE 0: C row-major [Mn, 1024]
//   MODE 1: C written as [B,H,T,Dh] (m=(b,t), n=(h,d))
// Block: 64x64 tile, 256 threads, 4x4 micro-tile, K-tile 16.
// ---------------------------------------------------------------------------
template <int MODE>
__global__ __launch_bounds__(256) void gemm_bias_kernel(
    const float* __restrict__ A, const float* __restrict__ W,
    const float* __restrict__ bias, float* __restrict__ C)
{
    __shared__ float As[16][65];   // [k][m], padded
    __shared__ float Ws[16][65];   // [k][n], padded

    const int tid = threadIdx.x;
    const int tx  = tid & 15;      // 0..15 -> n micro
    const int ty  = tid >> 4;      // 0..15 -> m micro
    const int m0  = blockIdx.y * 64;
    const int n0  = blockIdx.x * 64;

    const int r = tid >> 2;        // 0..63 : tile row to load
    const int c = (tid & 3) * 4;   // 0..12 : k offset (float4)

    const float* Ap = A + (size_t)(m0 + r) * 1024 + c;
    const float* Wp = W + (size_t)(n0 + r) * 1024 + c;

    float acc[4][4] = {};

    for (int k0 = 0; k0 < 1024; k0 += 16) {
        __syncthreads();
        float4 av = *(const float4*)(Ap + k0);
        float4 wv = *(const float4*)(Wp + k0);
        As[c + 0][r] = av.x; As[c + 1][r] = av.y;
        As[c + 2][r] = av.z; As[c + 3][r] = av.w;
        Ws[c + 0][r] = wv.x; Ws[c + 1][r] = wv.y;
        Ws[c + 2][r] = wv.z; Ws[c + 3][r] = wv.w;
        __syncthreads();

        #pragma unroll
        for (int kk = 0; kk < 16; kk++) {
            float a[4], w[4];
            #pragma unroll
            for (int i = 0; i < 4; i++) a[i] = As[kk][ty * 4 + i];
            #pragma unroll
            for (int j = 0; j < 4; j++) w[j] = Ws[kk][tx * 4 + j];
            #pragma unroll
            for (int i = 0; i < 4; i++)
                #pragma unroll
                for (int j = 0; j < 4; j++)
                    acc[i][j] = fmaf(a[i], w[j], acc[i][j]);
        }
    }

    const int n = n0 + tx * 4;
    const float4 bv = *(const float4*)(bias + n);

    #pragma unroll
    for (int i = 0; i < 4; i++) {
        const int m = m0 + ty * 4 + i;
        float4 o;
        o.x = acc[i][0] + bv.x;
        o.y = acc[i][1] + bv.y;
        o.z = acc[i][2] + bv.z;
        o.w = acc[i][3] + bv.w;
        if (MODE == 0) {
            *(float4*)(C + (size_t)m * Dn + n) = o;
        } else {
            const int b = m >> 11;            // m / Tn
            const int t = m & (Tn - 1);
            const int h = n >> 6;             // n / Dhn (tx*4 stays inside head)
            const int d = n & (Dhn - 1);
            *(float4*)(C + (((size_t)(b * Hn + h) * Tn + t) * Dhn + d)) = o;
        }
    }
}

// ---------------------------------------------------------------------------
// In-place RoPE on Qh and Kh ([B,H,T,Dh]); one thread per (d, d+32) pair.
// angle(t, i) = t * 10000^(-i/32), i = d in [0,32)
// out[d]    = x[d]*cos    - x[d+32]*sin
// out[d+32] = x[d+32]*cos + x[d]*sin
// ---------------------------------------------------------------------------
__global__ void rope_kernel(float* __restrict__ Q, float* __restrict__ K)
{
    const int idx = blockIdx.x * blockDim.x + threadIdx.x;
    const int total = Bn * Hn * Tn * 32;
    if (idx >= total) return;

    const int i  = idx & 31;
    const int t  = (idx >> 5) & (Tn - 1);
    const int bh = idx >> 16;                 // / (32 * 2048)

    // accurate powf/sincosf: phase error matters at t up to 2047
    const float invf = 1.0f / powf(10000.0f, (float)i * (1.0f / 32.0f));
    const float ang  = (float)t * invf;
    float sn, cs;
    sincosf(ang, &sn, &cs);

    const size_t base = ((size_t)bh * Tn + t) * Dhn + i;

    float q1 = Q[base], q2 = Q[base + 32];
    Q[base]      = q1 * cs - q2 * sn;
    Q[base + 32] = q2 * cs + q1 * sn;

    float k1 = K[base], k2 = K[base + 32];
    K[base]      = k1 * cs - k2 * sn;
    K[base + 32] = k2 * cs + k1 * sn;
}

// ---------------------------------------------------------------------------
// Flash-style attention, thread-per-query.
//   grid: (Tn/128, Bn*Hn), block: 128 threads
//   Each thread: q[64] + acc[64] in registers, online softmax,
//   K/V streamed through shared in 32-key tiles (broadcast LDS -> no conflicts)
//   Output written straight into [B,T,D] layout for the O projection.
// ---------------------------------------------------------------------------
__global__ __launch_bounds__(128) void attn_kernel(
    const float* __restrict__ Q, const float* __restrict__ K,
    const float* __restrict__ V, float* __restrict__ O)
{
    const int qi = blockIdx.x * 128 + threadIdx.x;   // query index in T
    const int bh = blockIdx.y;                       // b*Hn + h
    const int b  = bh >> 4;
    const int h  = bh & 15;

    const float4* Qp  = (const float4*)(Q + ((size_t)bh * Tn + qi) * Dhn);
    const float4* Kb4 = (const float4*)(K + (size_t)bh * Tn * Dhn);
    const float4* Vb4 = (const float4*)(V + (size_t)bh * Tn * Dhn);

    __shared__ float4 Ks[32][16];
    __shared__ float4 Vs[32][16];

    float4 q[16];
    #pragma unroll
    for (int i = 0; i < 16; i++) {
        float4 v = Qp[i];                  // fold 1/sqrt(64) into q
        v.x *= 0.125f; v.y *= 0.125f; v.z *= 0.125f; v.w *= 0.125f;
        q[i] = v;
    }

    float4 acc[16];
    #pragma unroll
    for (int i = 0; i < 16; i++) acc[i] = make_float4(0.f, 0.f, 0.f, 0.f);
    float m = -1e30f, l = 0.f;

    for (int kt = 0; kt < Tn; kt += 32) {
        __syncthreads();
        #pragma unroll
        for (int r = 0; r < 4; r++) {
            const int e   = threadIdx.x + r * 128;   // 0..511
            const int row = e >> 4, col = e & 15;
            Ks[row][col] = Kb4[(size_t)(kt + row) * 16 + col];
            Vs[row][col] = Vb4[(size_t)(kt + row) * 16 + col];
        }
        __syncthreads();

        // scores
        float s[32];
        #pragma unroll
        for (int j = 0; j < 32; j++) {
            float d0 = 0.f;
            #pragma unroll
            for (int i = 0; i < 16; i++) {
                const float4 kv = Ks[j][i];
                d0 = fmaf(q[i].x, kv.x, d0);
                d0 = fmaf(q[i].y, kv.y, d0);
                d0 = fmaf(q[i].z, kv.z, d0);
                d0 = fmaf(q[i].w, kv.w, d0);
            }
            s[j] = d0;
        }

        // online softmax update
        float tm = m;
        #pragma unroll
        for (int j = 0; j < 32; j++) tm = fmaxf(tm, s[j]);
        const float sc = __expf(m - tm);
        m = tm;
        l *= sc;
        #pragma unroll
        for (int i = 0; i < 16; i++) {
            acc[i].x *= sc; acc[i].y *= sc; acc[i].z *= sc; acc[i].w *= sc;
        }
        float ps = 0.f;
        #pragma unroll
        for (int j = 0; j < 32; j++) {
            const float p = __expf(s[j] - m);
            s[j] = p;
            ps += p;
        }
        l += ps;

        // acc += P @ V
        #pragma unroll
        for (int i = 0; i < 16; i++) {
            float4 a = acc[i];
            #pragma unroll
            for (int j = 0; j < 32; j++) {
                const float  p  = s[j];
                const float4 vv = Vs[j][i];
                a.x = fmaf(p, vv.x, a.x);
                a.y = fmaf(p, vv.y, a.y);
                a.z = fmaf(p, vv.z, a.z);
                a.w = fmaf(p, vv.w, a.w);
            }
            acc[i] = a;
        }
    }

    const float inv = 1.f / l;
    float4* Op = (float4*)(O + ((size_t)b * Tn + qi) * Dn + h * Dhn);
    #pragma unroll
    for (int i = 0; i < 16; i++) {
        float4 a = acc[i];
        a.x *= inv; a.y *= inv; a.z *= inv; a.w *= inv;
        Op[i] = a;
    }
}

// ---------------------------------------------------------------------------
extern "C" void kernel_launch(void* const* d_in, const int* in_sizes, int n_in,
                              void* d_out, int out_size)
{
    (void)in_sizes; (void)n_in; (void)out_size;
    const float* x  = (const float*)d_in[0];
    const float* Wq = (const float*)d_in[1];
    const float* bq = (const float*)d_in[2];
    const float* Wk = (const float*)d_in[3];
    const float* bk = (const float*)d_in[4];
    const float* Wv = (const float*)d_in[5];
    const float* bv = (const float*)d_in[6];
    const float* Wo = (const float*)d_in[7];
    const float* bo = (const float*)d_in[8];
    float* out = (float*)d_out;

    float *Qh, *Kh, *Vh, *attn;
    cudaGetSymbolAddress((void**)&Qh,   g_Qh);
    cudaGetSymbolAddress((void**)&Kh,   g_Kh);
    cudaGetSymbolAddress((void**)&Vh,   g_Vh);
    cudaGetSymbolAddress((void**)&attn, g_attn);

    const dim3 ggrid(Dn / 64, Mn / 64);   // (16, 64)

    gemm_bias_kernel<1><<<ggrid, 256>>>(x, Wq, bq, Qh);
    gemm_bias_kernel<1><<<ggrid, 256>>>(x, Wk, bk, Kh);
    gemm_bias_kernel<1><<<ggrid, 256>>>(x, Wv, bv, Vh);

    const int rope_total = Bn * Hn * Tn * 32;
    rope_kernel<<<(rope_total + 255) / 256, 256>>>(Qh, Kh);

    attn_kernel<<<dim3(Tn / 128, Bn * Hn), 128>>>(Qh, Kh, Vh, attn);

    gemm_bias_kernel<0><<<ggrid, 256>>>(attn, Wo, bo, out);
}

// round 4
// speedup vs baseline: 2.5960x; 2.5960x over previous
#include <cuda_runtime.h>
#include <math.h>
#include <cstdint>

// ---------------------------------------------------------------------------
// RoPE Multi-Head Attention on GB300 (sm_103 family-generic target!)
// R3: tcgen05 unavailable in this toolchain (ptxas targets sm_103, not
//     sm_103a). Use family-portable warp-level mma.sync tf32 (m16n8k8)
//     for the 4 projections AND the attention matmuls.
// ---------------------------------------------------------------------------

namespace {
constexpr int Bn  = 2;
constexpr int Tn  = 2048;
constexpr int Hn  = 16;
constexpr int Dhn = 64;
constexpr int Dn  = 1024;
constexpr int Mn  = Bn * Tn;       // 4096
}

__device__ float g_Qh[(size_t)Bn * Hn * Tn * Dhn];
__device__ float g_Kh[(size_t)Bn * Hn * Tn * Dhn];
__device__ float g_Vh[(size_t)Bn * Hn * Tn * Dhn];
__device__ float g_attn[(size_t)Bn * Tn * Dn];

// ----------------------------- mma helpers ---------------------------------
__device__ __forceinline__ uint32_t f2tf32(float x) {
    uint32_t r;
    asm("cvt.rna.tf32.f32 %0, %1;" : "=r"(r) : "f"(x));
    return r;
}

// D += A * B,  m16n8k8 tf32. c[0]:(g,2t) c[1]:(g,2t+1) c[2]:(g+8,2t) c[3]:(g+8,2t+1)
// a0:(g,t) a1:(g+8,t) a2:(g,t+4) a3:(g+8,t+4)   b0:(k=t,n=g) b1:(k=t+4,n=g)
__device__ __forceinline__ void mma_tf32(float* c,
    uint32_t a0, uint32_t a1, uint32_t a2, uint32_t a3, uint32_t b0, uint32_t b1)
{
    asm volatile(
        "mma.sync.aligned.m16n8k8.row.col.f32.tf32.tf32.f32 "
        "{%0,%1,%2,%3}, {%4,%5,%6,%7}, {%8,%9}, {%0,%1,%2,%3};\n"
        : "+f"(c[0]), "+f"(c[1]), "+f"(c[2]), "+f"(c[3])
        : "r"(a0), "r"(a1), "r"(a2), "r"(a3), "r"(b0), "r"(b1));
}

__device__ __forceinline__ uint32_t fbits(float x) { return __float_as_uint(x); }
__device__ __forceinline__ float tf32v(float x) { return __uint_as_float(f2tf32(x)); }

// ===========================================================================
// GEMM: C[m,n] = sum_k A[m,k] * W[n,k] + bias[n]   (A:[Mn,1024] W:[1024,1024])
// CTA 128x128, 256 thr (8 warps, 64x32 warp tiles), K-chunk 32, double buffer.
// Shared row stride 36 floats (36 mod 32 == 4 -> fragment reads conflict-free).
// MODE 0: C row-major [Mn,1024]; MODE 1: C scattered to [B,H,T,Dh].
// ===========================================================================
namespace {
constexpr int RS   = 36;            // smem row stride (floats)
constexpr int SBUF = 128 * RS;      // one buffer (floats)
constexpr int GEMM_SMEM_B = 4 * SBUF * 4;   // A0,A1,W0,W1 = 73728 bytes
}

template <int MODE>
__global__ __launch_bounds__(256)
void gemm_mma_kernel(const float* __restrict__ A, const float* __restrict__ W,
                     const float* __restrict__ bias, float* __restrict__ C)
{
    extern __shared__ float sm[];
    float* As = sm;              // [2][128][RS]
    float* Ws = sm + 2 * SBUF;   // [2][128][RS]

    const int tid  = threadIdx.x;
    const int lane = tid & 31;
    const int wid  = tid >> 5;
    const int g = lane >> 2, t = lane & 3;
    const int wm = wid >> 2, wn = wid & 3;        // warp tile origin (64m, 32n)

    const int m0 = blockIdx.y * 128, n0 = blockIdx.x * 128;
    const int row = tid >> 1, half = tid & 1;     // staging: row, 16-col half

    const float* Ap = A + (size_t)(m0 + row) * 1024 + half * 16;
    const float* Wp = W + (size_t)(n0 + row) * 1024 + half * 16;

    float acc[4][4][4];
    #pragma unroll
    for (int i = 0; i < 4; i++)
        #pragma unroll
        for (int j = 0; j < 4; j++)
            #pragma unroll
            for (int e = 0; e < 4; e++) acc[i][j][e] = 0.f;

    float4 la[4], lw[4];
    #pragma unroll
    for (int f = 0; f < 4; f++) {
        la[f] = *(const float4*)(Ap + f * 4);
        lw[f] = *(const float4*)(Wp + f * 4);
    }
    {   // store chunk 0 -> buffer 0
        float* Ad = As + row * RS + half * 16;
        float* Wd = Ws + row * RS + half * 16;
        #pragma unroll
        for (int f = 0; f < 4; f++) {
            Ad[f*4+0]=tf32v(la[f].x); Ad[f*4+1]=tf32v(la[f].y);
            Ad[f*4+2]=tf32v(la[f].z); Ad[f*4+3]=tf32v(la[f].w);
            Wd[f*4+0]=tf32v(lw[f].x); Wd[f*4+1]=tf32v(lw[f].y);
            Wd[f*4+2]=tf32v(lw[f].z); Wd[f*4+3]=tf32v(lw[f].w);
        }
    }

    for (int i = 0; i < 32; i++) {
        __syncthreads();
        if (i < 31) {
            const int k0 = (i + 1) * 32;
            #pragma unroll
            for (int f = 0; f < 4; f++) {
                la[f] = *(const float4*)(Ap + k0 + f * 4);
                lw[f] = *(const float4*)(Wp + k0 + f * 4);
            }
        }

        const float* Ab = As + (i & 1) * SBUF;
        const float* Bb = Ws + (i & 1) * SBUF;

        #pragma unroll
        for (int ks = 0; ks < 4; ks++) {
            const int k = ks * 8;
            uint32_t af[4][4];
            #pragma unroll
            for (int mt = 0; mt < 4; mt++) {
                const float* ar = Ab + (wm * 64 + mt * 16) * RS + k;
                af[mt][0] = fbits(ar[(g    ) * RS + t    ]);
                af[mt][1] = fbits(ar[(g + 8) * RS + t    ]);
                af[mt][2] = fbits(ar[(g    ) * RS + t + 4]);
                af[mt][3] = fbits(ar[(g + 8) * RS + t + 4]);
            }
            uint32_t bf[4][2];
            #pragma unroll
            for (int nt = 0; nt < 4; nt++) {
                const float* br = Bb + (wn * 32 + nt * 8 + g) * RS + k;
                bf[nt][0] = fbits(br[t]);
                bf[nt][1] = fbits(br[t + 4]);
            }
            #pragma unroll
            for (int mt = 0; mt < 4; mt++)
                #pragma unroll
                for (int nt = 0; nt < 4; nt++)
                    mma_tf32(acc[mt][nt], af[mt][0], af[mt][1], af[mt][2], af[mt][3],
                             bf[nt][0], bf[nt][1]);
        }

        if (i < 31) {
            __syncthreads();
            float* Ad = As + ((i + 1) & 1) * SBUF + row * RS + half * 16;
            float* Wd = Ws + ((i + 1) & 1) * SBUF + row * RS + half * 16;
            #pragma unroll
            for (int f = 0; f < 4; f++) {
                Ad[f*4+0]=tf32v(la[f].x); Ad[f*4+1]=tf32v(la[f].y);
                Ad[f*4+2]=tf32v(la[f].z); Ad[f*4+3]=tf32v(la[f].w);
                Wd[f*4+0]=tf32v(lw[f].x); Wd[f*4+1]=tf32v(lw[f].y);
                Wd[f*4+2]=tf32v(lw[f].z); Wd[f*4+3]=tf32v(lw[f].w);
            }
        }
    }

    // epilogue
    #pragma unroll
    for (int mt = 0; mt < 4; mt++) {
        const int r0 = m0 + wm * 64 + mt * 16 + g;
        #pragma unroll
        for (int nt = 0; nt < 4; nt++) {
            const int c = n0 + wn * 32 + nt * 8 + 2 * t;
            const float2 bv = *(const float2*)(bias + c);
            float2 o0 = make_float2(acc[mt][nt][0] + bv.x, acc[mt][nt][1] + bv.y);
            float2 o1 = make_float2(acc[mt][nt][2] + bv.x, acc[mt][nt][3] + bv.y);
            if (MODE == 0) {
                *(float2*)(C + (size_t)r0 * Dn + c)       = o0;
                *(float2*)(C + (size_t)(r0 + 8) * Dn + c) = o1;
            } else {
                const int h = c >> 6, d = c & 63;
                {
                    const int bb = r0 >> 11, tt = r0 & (Tn - 1);
                    *(float2*)(C + (((size_t)(bb * Hn + h) * Tn + tt) * Dhn + d)) = o0;
                }
                {
                    const int r1 = r0 + 8;
                    const int bb = r1 >> 11, tt = r1 & (Tn - 1);
                    *(float2*)(C + (((size_t)(bb * Hn + h) * Tn + tt) * Dhn + d)) = o1;
                }
            }
        }
    }
}

// ---------------------------------------------------------------------------
// In-place RoPE (unchanged)
// ---------------------------------------------------------------------------
__global__ void rope_kernel(float* __restrict__ Q, float* __restrict__ K)
{
    const int idx = blockIdx.x * blockDim.x + threadIdx.x;
    const int total = Bn * Hn * Tn * 32;
    if (idx >= total) return;

    const int i  = idx & 31;
    const int t  = (idx >> 5) & (Tn - 1);
    const int bh = idx >> 16;

    const float invf = 1.0f / powf(10000.0f, (float)i * (1.0f / 32.0f));
    const float ang  = (float)t * invf;
    float sn, cs;
    sincosf(ang, &sn, &cs);

    const size_t base = ((size_t)bh * Tn + t) * Dhn + i;

    float q1 = Q[base], q2 = Q[base + 32];
    Q[base]      = q1 * cs - q2 * sn;
    Q[base + 32] = q2 * cs + q1 * sn;

    float k1 = K[base], k2 = K[base + 32];
    K[base]      = k1 * cs - k2 * sn;
    K[base + 32] = k2 * cs + k1 * sn;
}

// ===========================================================================
// Flash attention with tf32 mma.sync.
// CTA: 64 queries x 1 head, 128 thr (4 warps, 16 q-rows each).
// K/V tiles: 64 keys, smem stride 68 (== 4 mod 32, conflict-free frags).
// P re-staged through Ks region (free after S mma) to A-fragment layout.
// ===========================================================================
__global__ __launch_bounds__(128)
void attn_mma_kernel(const float* __restrict__ Q, const float* __restrict__ K,
                     const float* __restrict__ V, float* __restrict__ O)
{
    __shared__ float Ks[64][68];
    __shared__ float Vs[64][68];

    const int tid  = threadIdx.x;
    const int lane = tid & 31;
    const int wid  = tid >> 5;
    const int g = lane >> 2, t = lane & 3;
    const int qt = blockIdx.x, bh = blockIdx.y;
    const int b = bh >> 4, h = bh & 15;

    const float* Qb = Q + (size_t)bh * Tn * Dhn;
    const float* Kb = K + (size_t)bh * Tn * Dhn;
    const float* Vb = V + (size_t)bh * Tn * Dhn;

    const int q0 = qt * 64 + wid * 16;

    // Q fragments (1/8 scale folded in), resident in registers
    uint32_t qf[8][4];
    #pragma unroll
    for (int kt = 0; kt < 8; kt++) {
        qf[kt][0] = f2tf32(Qb[(size_t)(q0 + g    ) * 64 + kt * 8 + t    ] * 0.125f);
        qf[kt][1] = f2tf32(Qb[(size_t)(q0 + g + 8) * 64 + kt * 8 + t    ] * 0.125f);
        qf[kt][2] = f2tf32(Qb[(size_t)(q0 + g    ) * 64 + kt * 8 + t + 4] * 0.125f);
        qf[kt][3] = f2tf32(Qb[(size_t)(q0 + g + 8) * 64 + kt * 8 + t + 4] * 0.125f);
    }

    float ao[8][4];
    #pragma unroll
    for (int d = 0; d < 8; d++)
        #pragma unroll
        for (int e = 0; e < 4; e++) ao[d][e] = 0.f;
    float m0v = -1e30f, m1v = -1e30f, l0 = 0.f, l1 = 0.f;

    const int row = tid >> 1, half = tid & 1;

    for (int kt0 = 0; kt0 < Tn; kt0 += 64) {
        __syncthreads();                       // prev iter done with Ks(P)/Vs
        {
            const float* Kp = Kb + (size_t)(kt0 + row) * 64 + half * 32;
            const float* Vp = Vb + (size_t)(kt0 + row) * 64 + half * 32;
            #pragma unroll
            for (int f = 0; f < 8; f++) {
                float4 kv = *(const float4*)(Kp + f * 4);
                float4 vv = *(const float4*)(Vp + f * 4);
                float* kd = &Ks[row][half * 32 + f * 4];
                float* vd = &Vs[row][half * 32 + f * 4];
                kd[0]=tf32v(kv.x); kd[1]=tf32v(kv.y); kd[2]=tf32v(kv.z); kd[3]=tf32v(kv.w);
                vd[0]=tf32v(vv.x); vd[1]=tf32v(vv.y); vd[2]=tf32v(vv.z); vd[3]=tf32v(vv.w);
            }
        }
        __syncthreads();

        // S = Q K^T (16x64 per warp)
        float sc[8][4];
        #pragma unroll
        for (int nt = 0; nt < 8; nt++) {
            #pragma unroll
            for (int e = 0; e < 4; e++) sc[nt][e] = 0.f;
            #pragma unroll
            for (int kt = 0; kt < 8; kt++) {
                uint32_t b0 = fbits(Ks[nt * 8 + g][kt * 8 + t]);
                uint32_t b1 = fbits(Ks[nt * 8 + g][kt * 8 + t + 4]);
                mma_tf32(sc[nt], qf[kt][0], qf[kt][1], qf[kt][2], qf[kt][3], b0, b1);
            }
        }

        // online softmax (rows g and g+8; reduce over quad lanes)
        float tm0 = -1e30f, tm1 = -1e30f;
        #pragma unroll
        for (int nt = 0; nt < 8; nt++) {
            tm0 = fmaxf(tm0, fmaxf(sc[nt][0], sc[nt][1]));
            tm1 = fmaxf(tm1, fmaxf(sc[nt][2], sc[nt][3]));
        }
        tm0 = fmaxf(tm0, __shfl_xor_sync(0xffffffffu, tm0, 1));
        tm0 = fmaxf(tm0, __shfl_xor_sync(0xffffffffu, tm0, 2));
        tm1 = fmaxf(tm1, __shfl_xor_sync(0xffffffffu, tm1, 1));
        tm1 = fmaxf(tm1, __shfl_xor_sync(0xffffffffu, tm1, 2));

        const float nm0 = fmaxf(m0v, tm0), nm1 = fmaxf(m1v, tm1);
        const float es0 = __expf(m0v - nm0), es1 = __expf(m1v - nm1);
        m0v = nm0; m1v = nm1;

        float s0 = 0.f, s1 = 0.f;
        #pragma unroll
        for (int nt = 0; nt < 8; nt++) {
            sc[nt][0] = __expf(sc[nt][0] - nm0);
            sc[nt][1] = __expf(sc[nt][1] - nm0);
            sc[nt][2] = __expf(sc[nt][2] - nm1);
            sc[nt][3] = __expf(sc[nt][3] - nm1);
            s0 += sc[nt][0] + sc[nt][1];
            s1 += sc[nt][2] + sc[nt][3];
        }
        s0 += __shfl_xor_sync(0xffffffffu, s0, 1);
        s0 += __shfl_xor_sync(0xffffffffu, s0, 2);
        s1 += __shfl_xor_sync(0xffffffffu, s1, 1);
        s1 += __shfl_xor_sync(0xffffffffu, s1, 2);
        l0 = l0 * es0 + s0;
        l1 = l1 * es1 + s1;
        #pragma unroll
        for (int d = 0; d < 8; d++) {
            ao[d][0] *= es0; ao[d][1] *= es0;
            ao[d][2] *= es1; ao[d][3] *= es1;
        }

        __syncthreads();                       // everyone done reading Ks
        // stage P (tf32) into Ks rows [wid*16, wid*16+16)
        float* Pb = &Ks[wid * 16][0];
        #pragma unroll
        for (int nt = 0; nt < 8; nt++) {
            *(float2*)(Pb + (size_t)(g    ) * 68 + nt * 8 + 2 * t) =
                make_float2(tf32v(sc[nt][0]), tf32v(sc[nt][1]));
            *(float2*)(Pb + (size_t)(g + 8) * 68 + nt * 8 + 2 * t) =
                make_float2(tf32v(sc[nt][2]), tf32v(sc[nt][3]));
        }
        __syncwarp();

        // O += P V (16x64 per warp)
        #pragma unroll
        for (int kt = 0; kt < 8; kt++) {
            uint32_t a0 = fbits(Pb[(size_t)(g    ) * 68 + kt * 8 + t    ]);
            uint32_t a1 = fbits(Pb[(size_t)(g + 8) * 68 + kt * 8 + t    ]);
            uint32_t a2 = fbits(Pb[(size_t)(g    ) * 68 + kt * 8 + t + 4]);
            uint32_t a3 = fbits(Pb[(size_t)(g + 8) * 68 + kt * 8 + t + 4]);
            #pragma unroll
            for (int dt = 0; dt < 8; dt++) {
                uint32_t b0 = fbits(Vs[kt * 8 + t    ][dt * 8 + g]);
                uint32_t b1 = fbits(Vs[kt * 8 + t + 4][dt * 8 + g]);
                mma_tf32(ao[dt], a0, a1, a2, a3, b0, b1);
            }
        }
    }

    const float inv0 = 1.f / l0, inv1 = 1.f / l1;
    const int r0 = qt * 64 + wid * 16 + g;
    #pragma unroll
    for (int dt = 0; dt < 8; dt++) {
        const int c = h * 64 + dt * 8 + 2 * t;
        *(float2*)(O + ((size_t)(b * Tn + r0) * Dn + c)) =
            make_float2(ao[dt][0] * inv0, ao[dt][1] * inv0);
        *(float2*)(O + ((size_t)(b * Tn + r0 + 8) * Dn + c)) =
            make_float2(ao[dt][2] * inv1, ao[dt][3] * inv1);
    }
}

// ---------------------------------------------------------------------------
extern "C" void kernel_launch(void* const* d_in, const int* in_sizes, int n_in,
                              void* d_out, int out_size)
{
    (void)in_sizes; (void)n_in; (void)out_size;
    const float* x  = (const float*)d_in[0];
    const float* Wq = (const float*)d_in[1];
    const float* bq = (const float*)d_in[2];
    const float* Wk = (const float*)d_in[3];
    const float* bk = (const float*)d_in[4];
    const float* Wv = (const float*)d_in[5];
    const float* bv = (const float*)d_in[6];
    const float* Wo = (const float*)d_in[7];
    const float* bo = (const float*)d_in[8];
    float* out = (float*)d_out;

    float *Qh, *Kh, *Vh, *attn;
    cudaGetSymbolAddress((void**)&Qh,   g_Qh);
    cudaGetSymbolAddress((void**)&Kh,   g_Kh);
    cudaGetSymbolAddress((void**)&Vh,   g_Vh);
    cudaGetSymbolAddress((void**)&attn, g_attn);

    cudaFuncSetAttribute(gemm_mma_kernel<0>, cudaFuncAttributeMaxDynamicSharedMemorySize, GEMM_SMEM_B);
    cudaFuncSetAttribute(gemm_mma_kernel<1>, cudaFuncAttributeMaxDynamicSharedMemorySize, GEMM_SMEM_B);

    const dim3 ggrid(Dn / 128, Mn / 128);   // (8, 32)

    gemm_mma_kernel<1><<<ggrid, 256, GEMM_SMEM_B>>>(x, Wq, bq, Qh);
    gemm_mma_kernel<1><<<ggrid, 256, GEMM_SMEM_B>>>(x, Wk, bk, Kh);
    gemm_mma_kernel<1><<<ggrid, 256, GEMM_SMEM_B>>>(x, Wv, bv, Vh);

    const int rope_total = Bn * Hn * Tn * 32;
    rope_kernel<<<(rope_total + 255) / 256, 256>>>(Qh, Kh);

    attn_mma_kernel<<<dim3(Tn / 64, Bn * Hn), 128>>>(Qh, Kh, Vh, attn);

    gemm_mma_kernel<0><<<ggrid, 256, GEMM_SMEM_B>>>(attn, Wo, bo, out);
}

// round 8
// speedup vs baseline: 5.7217x; 2.2041x over previous
#include <cuda_runtime.h>
#include <cuda_fp16.h>
#include <math.h>
#include <cstdint>

// ---------------------------------------------------------------------------
// RoPE MHA on GB300 (sm_103 family-generic target).
// R5: fp16 m16n8k16 mma + ldmatrix + cp.async.
//   gemm<1>(x,Wq)->Qf fp32 ; gemm<1>(x,Wk)->Kf fp32 ; gemm<2>(x,Wv)->Vh fp16
//   rope(Qf,Kf)->Qh,Kh fp16 (fp32 math, Q pre-scaled by 1/8)
//   attn(Qh,Kh,Vh)->attnH fp16   (flash, all-register P)
//   gemm<0>(attnH,Wo)+bias -> out fp32
// ---------------------------------------------------------------------------

namespace {
constexpr int Bn=2, Tn=2048, Hn=16, Dhn=64, Dn=1024, Mn=4096;
}

__device__ float  g_Qf[(size_t)Mn*Dn];
__device__ float  g_Kf[(size_t)Mn*Dn];
__device__ __half g_Qh[(size_t)Mn*Dn];
__device__ __half g_Kh[(size_t)Mn*Dn];
__device__ __half g_Vh[(size_t)Mn*Dn];
__device__ __half g_attn[(size_t)Mn*Dn];

// ----------------------------- helpers ------------------------------------
__device__ __forceinline__ uint32_t smem_u32(const void* p) {
    uint32_t a;
    asm("{ .reg .u64 t; cvta.to.shared.u64 t, %1; cvt.u32.u64 %0, t; }"
        : "=r"(a) : "l"(p));
    return a;
}
__device__ __forceinline__ uint32_t pkh2(float lo, float hi) {
    __half2 h = __floats2half2_rn(lo, hi);
    return *reinterpret_cast<uint32_t*>(&h);
}
__device__ __forceinline__ void mma16816(float* c, const uint32_t* a,
                                         uint32_t b0, uint32_t b1) {
    asm volatile(
        "mma.sync.aligned.m16n8k16.row.col.f32.f16.f16.f32 "
        "{%0,%1,%2,%3},{%4,%5,%6,%7},{%8,%9},{%0,%1,%2,%3};"
        : "+f"(c[0]), "+f"(c[1]), "+f"(c[2]), "+f"(c[3])
        : "r"(a[0]), "r"(a[1]), "r"(a[2]), "r"(a[3]), "r"(b0), "r"(b1));
}
__device__ __forceinline__ void ldsm4(uint32_t* r, uint32_t addr) {
    asm volatile("ldmatrix.sync.aligned.m8n8.x4.shared.b16 {%0,%1,%2,%3}, [%4];"
        : "=r"(r[0]), "=r"(r[1]), "=r"(r[2]), "=r"(r[3]) : "r"(addr));
}
__device__ __forceinline__ void ldsm4t(uint32_t* r, uint32_t addr) {
    asm volatile("ldmatrix.sync.aligned.m8n8.x4.trans.shared.b16 {%0,%1,%2,%3}, [%4];"
        : "=r"(r[0]), "=r"(r[1]), "=r"(r[2]), "=r"(r[3]) : "r"(addr));
}
#define CP_ASYNC16(dst, src) \
    asm volatile("cp.async.cg.shared.global [%0], [%1], 16;" :: "r"(dst), "l"(src))
#define CP_COMMIT() asm volatile("cp.async.commit_group;" ::: "memory")
#define CP_WAIT(n)  asm volatile("cp.async.wait_group %0;" :: "n"(n) : "memory")

// ===========================================================================
// GEMM: C[m,n] = sum_k A[m,k]*W[n,k] + bias[n]
//   CTA 128x128, 256 thr, 8 warps (64x32 tiles), K-chunk 32, double buffer.
//   fp16 operands in smem (stride 56 halves: 112B, 16B-aligned, ldsm
//   bank-phase -4j -> conflict-free). W fp32->fp16 in regs; A fp32 (AH=0)
//   or fp16 (AH=1).
//   MODE 0: fp32 row-major + bias (final out)
//   MODE 1: fp32 scattered [B,H,T,Dh], (acc+bias)*oscale   (Q, K)
//   MODE 2: fp16 scattered [B,H,T,Dh], acc+bias            (V)
// ===========================================================================
namespace {
constexpr int RSH   = 56;            // smem row stride (halves)
constexpr int SBUFH = 128 * RSH;     // 7168 halves / buffer
constexpr int GEMM_SMEM_B = 4 * SBUFH * 2;   // 57344 bytes
}

template <int MODE, int AH>
__global__ __launch_bounds__(256)
void gemm_h_kernel(const void* __restrict__ Av, const float* __restrict__ W,
                   const float* __restrict__ bias, void* __restrict__ Cv,
                   float oscale)
{
    extern __shared__ __half smh[];
    const uint32_t ub = smem_u32(smh);

    const int tid  = threadIdx.x;
    const int lane = tid & 31;
    const int wid  = tid >> 5;
    const int g = lane >> 2, t = lane & 3;
    const int lm   = lane & 15;
    const int lh16 = (lane >> 4) << 4;           // byte offset of k-halfblock
    const int wm = wid >> 2, wn = wid & 3;

    const int m0 = blockIdx.y * 128, n0 = blockIdx.x * 128;
    const int row = tid >> 1, hf = tid & 1;

    const float*  Af = (const float*)Av;
    const __half* Ah = (const __half*)Av;

    float acc[4][4][4];
    #pragma unroll
    for (int i = 0; i < 4; i++)
        #pragma unroll
        for (int j = 0; j < 4; j++)
            #pragma unroll
            for (int e = 0; e < 4; e++) acc[i][j][e] = 0.f;

    float4 la[4], lw[4];
    uint4  lah[2];

    auto loadA = [&](int k0) {
        if (AH) {
            const __half* p = Ah + (size_t)(m0 + row) * 1024 + k0 + hf * 16;
            lah[0] = *(const uint4*)(p);
            lah[1] = *(const uint4*)(p + 8);
        } else {
            const float* p = Af + (size_t)(m0 + row) * 1024 + k0 + hf * 16;
            #pragma unroll
            for (int f = 0; f < 4; f++) la[f] = *(const float4*)(p + f * 4);
        }
    };
    auto loadW = [&](int k0) {
        const float* p = W + (size_t)(n0 + row) * 1024 + k0 + hf * 16;
        #pragma unroll
        for (int f = 0; f < 4; f++) lw[f] = *(const float4*)(p + f * 4);
    };
    auto storeBuf = [&](int b) {
        __half* Ad = smh + b * SBUFH + row * RSH + hf * 16;
        __half* Wd = smh + (2 + b) * SBUFH + row * RSH + hf * 16;
        if (AH) {
            *(uint4*)Ad = lah[0];
            *(uint4*)(Ad + 8) = lah[1];
        } else {
            uint32_t h2[8];
            #pragma unroll
            for (int f = 0; f < 4; f++) {
                h2[2*f]   = pkh2(la[f].x, la[f].y);
                h2[2*f+1] = pkh2(la[f].z, la[f].w);
            }
            *(uint4*)Ad       = make_uint4(h2[0], h2[1], h2[2], h2[3]);
            *(uint4*)(Ad + 8) = make_uint4(h2[4], h2[5], h2[6], h2[7]);
        }
        uint32_t w2[8];
        #pragma unroll
        for (int f = 0; f < 4; f++) {
            w2[2*f]   = pkh2(lw[f].x, lw[f].y);
            w2[2*f+1] = pkh2(lw[f].z, lw[f].w);
        }
        *(uint4*)Wd       = make_uint4(w2[0], w2[1], w2[2], w2[3]);
        *(uint4*)(Wd + 8) = make_uint4(w2[4], w2[5], w2[6], w2[7]);
    };

    loadA(0); loadW(0); storeBuf(0);

    for (int i = 0; i < 32; i++) {
        __syncthreads();
        if (i < 31) { loadA((i + 1) * 32); loadW((i + 1) * 32); }

        const int b = i & 1;
        const uint32_t uA = ub + b * SBUFH * 2;
        const uint32_t uW = ub + (2 + b) * SBUFH * 2;

        #pragma unroll
        for (int ks = 0; ks < 2; ks++) {
            uint32_t af[4][4];
            #pragma unroll
            for (int mt = 0; mt < 4; mt++)
                ldsm4(af[mt], uA + (wm*64 + mt*16 + lm) * 112 + ks*32 + lh16);
            uint32_t bf[2][4];
            #pragma unroll
            for (int nt2 = 0; nt2 < 2; nt2++)
                ldsm4(bf[nt2], uW + (wn*32 + nt2*16 + lm) * 112 + ks*32 + lh16);
            #pragma unroll
            for (int mt = 0; mt < 4; mt++)
                #pragma unroll
                for (int nt = 0; nt < 4; nt++) {
                    const int p = nt >> 1, q = nt & 1;
                    mma16816(acc[mt][nt], af[mt], bf[p][q], bf[p][2 + q]);
                }
        }

        if (i < 31) { __syncthreads(); storeBuf((i + 1) & 1); }
    }

    // epilogue
    #pragma unroll
    for (int mt = 0; mt < 4; mt++) {
        const int r0 = m0 + wm * 64 + mt * 16 + g;
        #pragma unroll
        for (int nt = 0; nt < 4; nt++) {
            const int c = n0 + wn * 32 + nt * 8 + 2 * t;
            const float2 bv = *(const float2*)(bias + c);
            float o00 = acc[mt][nt][0] + bv.x, o01 = acc[mt][nt][1] + bv.y;
            float o10 = acc[mt][nt][2] + bv.x, o11 = acc[mt][nt][3] + bv.y;
            if (MODE == 0) {
                float* C = (float*)Cv;
                *(float2*)(C + (size_t)r0 * Dn + c)       = make_float2(o00, o01);
                *(float2*)(C + (size_t)(r0 + 8) * Dn + c) = make_float2(o10, o11);
            } else {
                const int h = c >> 6, d = c & 63;
                const int bb0 = r0 >> 11, tt0 = r0 & (Tn - 1);
                const int r1 = r0 + 8;
                const int bb1 = r1 >> 11, tt1 = r1 & (Tn - 1);
                const size_t p0 = ((size_t)(bb0 * Hn + h) * Tn + tt0) * Dhn + d;
                const size_t p1 = ((size_t)(bb1 * Hn + h) * Tn + tt1) * Dhn + d;
                if (MODE == 1) {
                    float* C = (float*)Cv;
                    *(float2*)(C + p0) = make_float2(o00 * oscale, o01 * oscale);
                    *(float2*)(C + p1) = make_float2(o10 * oscale, o11 * oscale);
                } else {
                    __half* C = (__half*)Cv;
                    *(uint32_t*)(C + p0) = pkh2(o00, o01);
                    *(uint32_t*)(C + p1) = pkh2(o10, o11);
                }
            }
        }
    }
}

// ---------------------------------------------------------------------------
// RoPE: read fp32 Qf/Kf, rotate in fp32, write fp16 (single rounding).
// ---------------------------------------------------------------------------
__global__ void rope_h_kernel(const float* __restrict__ Qf, const float* __restrict__ Kf,
                              __half* __restrict__ Qh, __half* __restrict__ Kh)
{
    const int idx = blockIdx.x * blockDim.x + threadIdx.x;
    const int total = Bn * Hn * Tn * 32;
    if (idx >= total) return;

    const int i  = idx & 31;
    const int t  = (idx >> 5) & (Tn - 1);
    const int bh = idx >> 16;

    const float invf = 1.0f / powf(10000.0f, (float)i * (1.0f / 32.0f));
    const float ang  = (float)t * invf;
    float sn, cs;
    sincosf(ang, &sn, &cs);

    const size_t base = ((size_t)bh * Tn + t) * Dhn + i;

    const float q1 = Qf[base], q2 = Qf[base + 32];
    Qh[base]      = __float2half_rn(q1 * cs - q2 * sn);
    Qh[base + 32] = __float2half_rn(q2 * cs + q1 * sn);

    const float k1 = Kf[base], k2 = Kf[base + 32];
    Kh[base]      = __float2half_rn(k1 * cs - k2 * sn);
    Kh[base + 32] = __float2half_rn(k2 * cs + k1 * sn);
}

// ===========================================================================
// Flash attention, fp16 mma + cp.async double-buffered K/V.
//   CTA: 64 queries, 128 thr (4 warps x 16 q). Smem stride 72 halves (144B).
//   Layout (bytes): Q 0..9216 | K0 | K1 | V0 | V1  (each 9216)
//   P never touches smem: S C-frags repacked to A-frags in registers.
// ===========================================================================
namespace { constexpr int ATTN_SMEM_B = 5 * 9216; }

__global__ __launch_bounds__(128)
void attn_h_kernel(const __half* __restrict__ Q, const __half* __restrict__ K,
                   const __half* __restrict__ V, __half* __restrict__ O)
{
    extern __shared__ __half asm_[];
    const uint32_t ub = smem_u32(asm_);

    const int tid  = threadIdx.x;
    const int lane = tid & 31;
    const int wid  = tid >> 5;
    const int g = lane >> 2, t = lane & 3;
    const int lm   = lane & 15;
    const int lh16 = (lane >> 4) << 4;

    const int qt = blockIdx.x, bh = blockIdx.y;
    const int b = bh >> 4, h = bh & 15;

    const char* Qg = (const char*)(Q + (size_t)bh * Tn * 64 + (size_t)qt * 64 * 64);
    const char* Kg = (const char*)(K + (size_t)bh * Tn * 64);
    const char* Vg = (const char*)(V + (size_t)bh * Tn * 64);

    const uint32_t uQ = ub;
    const uint32_t uK[2] = { ub + 9216,  ub + 2 * 9216 };
    const uint32_t uV[2] = { ub + 3 * 9216, ub + 4 * 9216 };

    // prologue: Q + tile0 K/V (tiles are 8KB contiguous in global)
    #pragma unroll
    for (int c = 0; c < 4; c++) {
        const int ci = tid + c * 128;
        const uint32_t doff = (ci >> 3) * 144 + (ci & 7) * 16;
        CP_ASYNC16(uQ    + doff, Qg + ci * 16);
        CP_ASYNC16(uK[0] + doff, Kg + ci * 16);
        CP_ASYNC16(uV[0] + doff, Vg + ci * 16);
    }
    CP_COMMIT();
    CP_WAIT(0);
    __syncthreads();

    // Q fragments (Q already scaled by 1/8)
    uint32_t qf[4][4];
    #pragma unroll
    for (int kb = 0; kb < 4; kb++)
        ldsm4(qf[kb], uQ + (wid*16 + lm) * 144 + kb*32 + lh16);

    float ao[8][4];
    #pragma unroll
    for (int d = 0; d < 8; d++)
        #pragma unroll
        for (int e = 0; e < 4; e++) ao[d][e] = 0.f;
    float m0v = -1e30f, m1v = -1e30f, l0 = 0.f, l1 = 0.f;

    for (int i = 0; i < 32; i++) {
        if (i + 1 < 32) {
            const int s = (i + 1) & 1;
            const char* Kn = Kg + (size_t)(i + 1) * 8192;
            const char* Vn = Vg + (size_t)(i + 1) * 8192;
            #pragma unroll
            for (int c = 0; c < 4; c++) {
                const int ci = tid + c * 128;
                const uint32_t doff = (ci >> 3) * 144 + (ci & 7) * 16;
                CP_ASYNC16(uK[s] + doff, Kn + ci * 16);
                CP_ASYNC16(uV[s] + doff, Vn + ci * 16);
            }
            CP_COMMIT();
            CP_WAIT(1);
        } else {
            CP_WAIT(0);
        }
        __syncthreads();

        const int s = i & 1;

        // S = Q K^T  (16q x 64k per warp)
        float sc[8][4];
        #pragma unroll
        for (int nt = 0; nt < 8; nt++)
            #pragma unroll
            for (int e = 0; e < 4; e++) sc[nt][e] = 0.f;
        #pragma unroll
        for (int nt2 = 0; nt2 < 4; nt2++) {
            #pragma unroll
            for (int kb = 0; kb < 4; kb++) {
                uint32_t bf[4];
                ldsm4(bf, uK[s] + (nt2*16 + lm) * 144 + kb*32 + lh16);
                mma16816(sc[2*nt2],     qf[kb], bf[0], bf[2]);
                mma16816(sc[2*nt2 + 1], qf[kb], bf[1], bf[3]);
            }
        }

        // online softmax (rows g / g+8, quad reduce)
        float tm0 = -1e30f, tm1 = -1e30f;
        #pragma unroll
        for (int nt = 0; nt < 8; nt++) {
            tm0 = fmaxf(tm0, fmaxf(sc[nt][0], sc[nt][1]));
            tm1 = fmaxf(tm1, fmaxf(sc[nt][2], sc[nt][3]));
        }
        tm0 = fmaxf(tm0, __shfl_xor_sync(0xffffffffu, tm0, 1));
        tm0 = fmaxf(tm0, __shfl_xor_sync(0xffffffffu, tm0, 2));
        tm1 = fmaxf(tm1, __shfl_xor_sync(0xffffffffu, tm1, 1));
        tm1 = fmaxf(tm1, __shfl_xor_sync(0xffffffffu, tm1, 2));

        const float nm0 = fmaxf(m0v, tm0), nm1 = fmaxf(m1v, tm1);
        const float es0 = __expf(m0v - nm0), es1 = __expf(m1v - nm1);
        m0v = nm0; m1v = nm1;

        float s0 = 0.f, s1 = 0.f;
        #pragma unroll
        for (int nt = 0; nt < 8; nt++) {
            sc[nt][0] = __expf(sc[nt][0] - nm0);
            sc[nt][1] = __expf(sc[nt][1] - nm0);
            sc[nt][2] = __expf(sc[nt][2] - nm1);
            sc[nt][3] = __expf(sc[nt][3] - nm1);
            s0 += sc[nt][0] + sc[nt][1];
            s1 += sc[nt][2] + sc[nt][3];
        }
        s0 += __shfl_xor_sync(0xffffffffu, s0, 1);
        s0 += __shfl_xor_sync(0xffffffffu, s0, 2);
        s1 += __shfl_xor_sync(0xffffffffu, s1, 1);
        s1 += __shfl_xor_sync(0xffffffffu, s1, 2);
        l0 = l0 * es0 + s0;
        l1 = l1 * es1 + s1;
        #pragma unroll
        for (int d = 0; d < 8; d++) {
            ao[d][0] *= es0; ao[d][1] *= es0;
            ao[d][2] *= es1; ao[d][3] *= es1;
        }

        // O += P V : P fragments straight from sc (register repack)
        #pragma unroll
        for (int kb2 = 0; kb2 < 4; kb2++) {
            uint32_t pa[4];
            pa[0] = pkh2(sc[2*kb2][0],     sc[2*kb2][1]);
            pa[1] = pkh2(sc[2*kb2][2],     sc[2*kb2][3]);
            pa[2] = pkh2(sc[2*kb2 + 1][0], sc[2*kb2 + 1][1]);
            pa[3] = pkh2(sc[2*kb2 + 1][2], sc[2*kb2 + 1][3]);
            #pragma unroll
            for (int dp = 0; dp < 4; dp++) {
                uint32_t vf[4];
                ldsm4t(vf, uV[s] + (kb2*16 + lm) * 144 + dp*32 + lh16);
                mma16816(ao[2*dp],     pa, vf[0], vf[1]);
                mma16816(ao[2*dp + 1], pa, vf[2], vf[3]);
            }
        }
        __syncthreads();   // all warps done with stage s before re-issue
    }

    const float inv0 = 1.f / l0, inv1 = 1.f / l1;
    const int r0 = qt * 64 + wid * 16 + g;
    const size_t mrow0 = (size_t)(b * Tn + r0) * Dn;
    const size_t mrow1 = (size_t)(b * Tn + r0 + 8) * Dn;
    #pragma unroll
    for (int dt = 0; dt < 8; dt++) {
        const int c = h * 64 + dt * 8 + 2 * t;
        *(uint32_t*)(O + mrow0 + c) = pkh2(ao[dt][0] * inv0, ao[dt][1] * inv0);
        *(uint32_t*)(O + mrow1 + c) = pkh2(ao[dt][2] * inv1, ao[dt][3] * inv1);
    }
}

// ---------------------------------------------------------------------------
extern "C" void kernel_launch(void* const* d_in, const int* in_sizes, int n_in,
                              void* d_out, int out_size)
{
    (void)in_sizes; (void)n_in; (void)out_size;
    const float* x  = (const float*)d_in[0];
    const float* Wq = (const float*)d_in[1];
    const float* bq = (const float*)d_in[2];
    const float* Wk = (const float*)d_in[3];
    const float* bk = (const float*)d_in[4];
    const float* Wv = (const float*)d_in[5];
    const float* bv = (const float*)d_in[6];
    const float* Wo = (const float*)d_in[7];
    const float* bo = (const float*)d_in[8];
    float* out = (float*)d_out;

    float *Qf, *Kf;
    __half *Qh, *Kh, *Vh, *attn;
    cudaGetSymbolAddress((void**)&Qf,   g_Qf);
    cudaGetSymbolAddress((void**)&Kf,   g_Kf);
    cudaGetSymbolAddress((void**)&Qh,   g_Qh);
    cudaGetSymbolAddress((void**)&Kh,   g_Kh);
    cudaGetSymbolAddress((void**)&Vh,   g_Vh);
    cudaGetSymbolAddress((void**)&attn, g_attn);

    cudaFuncSetAttribute(gemm_h_kernel<0,1>, cudaFuncAttributeMaxDynamicSharedMemorySize, GEMM_SMEM_B);
    cudaFuncSetAttribute(gemm_h_kernel<1,0>, cudaFuncAttributeMaxDynamicSharedMemorySize, GEMM_SMEM_B);
    cudaFuncSetAttribute(gemm_h_kernel<2,0>, cudaFuncAttributeMaxDynamicSharedMemorySize, GEMM_SMEM_B);

    const dim3 ggrid(Dn / 128, Mn / 128);   // (8, 32)

    gemm_h_kernel<1,0><<<ggrid, 256, GEMM_SMEM_B>>>(x, Wq, bq, Qf, 0.125f);
    gemm_h_kernel<1,0><<<ggrid, 256, GEMM_SMEM_B>>>(x, Wk, bk, Kf, 1.0f);
    gemm_h_kernel<2,0><<<ggrid, 256, GEMM_SMEM_B>>>(x, Wv, bv, Vh, 1.0f);

    const int rope_total = Bn * Hn * Tn * 32;
    rope_h_kernel<<<(rope_total + 255) / 256, 256>>>(Qf, Kf, Qh, Kh);

    attn_h_kernel<<<dim3(Tn / 64, Bn * Hn), 128, ATTN_SMEM_B>>>(Qh, Kh, Vh, attn);

    gemm_h_kernel<0,1><<<ggrid, 256, GEMM_SMEM_B>>>(attn, Wo, bo, out, 1.0f);
}

// round 10
// speedup vs baseline: 6.5687x; 1.1480x over previous
#include <cuda_runtime.h>
#include <cuda_fp16.h>
#include <math.h>
#include <cstdint>

// ---------------------------------------------------------------------------
// RoPE MHA on GB300 (sm_103 family-generic target).
// R9: pre-converted fp16 operands; fused QKV GEMM with 3-stage cp.async
//     pipeline (pure-HMMA mainloop); attention widened to 128q/CTA.
// ---------------------------------------------------------------------------

namespace {
constexpr int Bn=2, Tn=2048, Hn=16, Dhn=64, Dn=1024, Mn=4096;
}

__device__ __half g_xh[(size_t)Mn*Dn];
__device__ __half g_Wqh[(size_t)Dn*Dn];
__device__ __half g_Wkh[(size_t)Dn*Dn];
__device__ __half g_Wvh[(size_t)Dn*Dn];
__device__ __half g_Woh[(size_t)Dn*Dn];
__device__ float  g_Qf[(size_t)Mn*Dn];
__device__ float  g_Kf[(size_t)Mn*Dn];
__device__ __half g_Qh[(size_t)Mn*Dn];
__device__ __half g_Kh[(size_t)Mn*Dn];
__device__ __half g_Vh[(size_t)Mn*Dn];
__device__ __half g_attn[(size_t)Mn*Dn];

// ----------------------------- helpers ------------------------------------
__device__ __forceinline__ uint32_t smem_u32(const void* p) {
    uint32_t a;
    asm("{ .reg .u64 t; cvta.to.shared.u64 t, %1; cvt.u32.u64 %0, t; }"
        : "=r"(a) : "l"(p));
    return a;
}
__device__ __forceinline__ uint32_t pkh2(float lo, float hi) {
    __half2 h = __floats2half2_rn(lo, hi);
    return *reinterpret_cast<uint32_t*>(&h);
}
__device__ __forceinline__ void mma16816(float* c, const uint32_t* a,
                                         uint32_t b0, uint32_t b1) {
    asm volatile(
        "mma.sync.aligned.m16n8k16.row.col.f32.f16.f16.f32 "
        "{%0,%1,%2,%3},{%4,%5,%6,%7},{%8,%9},{%0,%1,%2,%3};"
        : "+f"(c[0]), "+f"(c[1]), "+f"(c[2]), "+f"(c[3])
        : "r"(a[0]), "r"(a[1]), "r"(a[2]), "r"(a[3]), "r"(b0), "r"(b1));
}
__device__ __forceinline__ void ldsm4(uint32_t* r, uint32_t addr) {
    asm volatile("ldmatrix.sync.aligned.m8n8.x4.shared.b16 {%0,%1,%2,%3}, [%4];"
        : "=r"(r[0]), "=r"(r[1]), "=r"(r[2]), "=r"(r[3]) : "r"(addr));
}
__device__ __forceinline__ void ldsm4t(uint32_t* r, uint32_t addr) {
    asm volatile("ldmatrix.sync.aligned.m8n8.x4.trans.shared.b16 {%0,%1,%2,%3}, [%4];"
        : "=r"(r[0]), "=r"(r[1]), "=r"(r[2]), "=r"(r[3]) : "r"(addr));
}
#define CP_ASYNC16(dst, src) \
    asm volatile("cp.async.cg.shared.global [%0], [%1], 16;" :: "r"(dst), "l"(src))
#define CP_COMMIT() asm volatile("cp.async.commit_group;" ::: "memory")
#define CP_WAIT(n)  asm volatile("cp.async.wait_group %0;" :: "n"(n) : "memory")

// ---------------------------------------------------------------------------
// fp32 -> fp16 conversion (vectorized)
// ---------------------------------------------------------------------------
__global__ void cvt_h_kernel(const float* __restrict__ in, __half* __restrict__ out, int n4)
{
    const int i = blockIdx.x * blockDim.x + threadIdx.x;
    if (i >= n4) return;
    const float4 v = ((const float4*)in)[i];
    uint2 o;
    o.x = pkh2(v.x, v.y);
    o.y = pkh2(v.z, v.w);
    ((uint2*)out)[i] = o;
}

// ===========================================================================
// GEMM mainloop: acc[4][4][4] = A[128,1024] x W[128,1024]^T tile product.
//   All-fp16, 3-stage cp.async, K-chunk 64, 1 __syncthreads per iter.
//   smem: A stages 0..2 at 0,18432,36864 ; W stages at 55296+...
//   Row stride 144B (72 halves).
// ===========================================================================
namespace {
constexpr int STGB  = 18432;            // bytes per matrix-stage (128 x 144)
constexpr int GSMEM = 6 * STGB;         // 110592 bytes
constexpr int NIT   = 16;               // 1024 / 64
}

__device__ __forceinline__ void gload64(uint32_t dst, const __half* src,
                                        int row, int hf, int k0)
{
    const char* s = (const char*)(src + (size_t)row * 1024 + k0 + hf * 32);
    const uint32_t d = dst + row * 144 + hf * 64;
    CP_ASYNC16(d,      s);
    CP_ASYNC16(d + 16, s + 16);
    CP_ASYNC16(d + 32, s + 32);
    CP_ASYNC16(d + 48, s + 48);
}

__device__ __forceinline__ void gemm_mainloop(const __half* Ag, const __half* Wg,
                                              uint32_t ub, float (&acc)[4][4][4])
{
    const int tid  = threadIdx.x;
    const int lane = tid & 31;
    const int wid  = tid >> 5;
    const int lm   = lane & 15;
    const int lh16 = (lane >> 4) << 4;
    const int wm = wid >> 2, wn = wid & 3;
    const int row = tid >> 1, hf = tid & 1;

    #pragma unroll
    for (int i = 0; i < 4; i++)
        #pragma unroll
        for (int j = 0; j < 4; j++)
            #pragma unroll
            for (int e = 0; e < 4; e++) acc[i][j][e] = 0.f;

    // prologue: chunks 0,1
    gload64(ub,            Ag, row, hf, 0);
    gload64(ub + 3 * STGB, Wg, row, hf, 0);
    CP_COMMIT();
    gload64(ub + STGB,           Ag, row, hf, 64);
    gload64(ub + 3 * STGB + STGB, Wg, row, hf, 64);
    CP_COMMIT();

    for (int i = 0; i < NIT; i++) {
        CP_WAIT(1);
        __syncthreads();
        if (i + 2 < NIT) {
            const int s = (i + 2) % 3;
            gload64(ub + s * STGB,           Ag, row, hf, (i + 2) * 64);
            gload64(ub + (3 + s) * STGB,     Wg, row, hf, (i + 2) * 64);
        }
        CP_COMMIT();

        const uint32_t uA = ub + (i % 3) * STGB;
        const uint32_t uW = ub + (3 + i % 3) * STGB;
        #pragma unroll
        for (int kb = 0; kb < 4; kb++) {
            uint32_t af[4][4];
            #pragma unroll
            for (int mt = 0; mt < 4; mt++)
                ldsm4(af[mt], uA + (wm*64 + mt*16 + lm) * 144 + kb*32 + lh16);
            uint32_t bf[2][4];
            #pragma unroll
            for (int nt2 = 0; nt2 < 2; nt2++)
                ldsm4(bf[nt2], uW + (wn*32 + nt2*16 + lm) * 144 + kb*32 + lh16);
            #pragma unroll
            for (int mt = 0; mt < 4; mt++)
                #pragma unroll
                for (int nt = 0; nt < 4; nt++) {
                    const int p = nt >> 1, q = nt & 1;
                    mma16816(acc[mt][nt], af[mt], bf[p][q], bf[p][2 + q]);
                }
        }
    }
}

// ===========================================================================
// Fused QKV projection. grid (24, 32): which = bx/8, n0 = (bx%8)*128.
//   Q -> Qf fp32 * 0.125 scatter[B,H,T,Dh]; K -> Kf fp32 scatter; V -> Vh fp16.
// ===========================================================================
__global__ __launch_bounds__(256)
void gemm_qkv_kernel(const __half* __restrict__ xh,
                     const __half* __restrict__ Wqh, const __half* __restrict__ Wkh,
                     const __half* __restrict__ Wvh,
                     const float* __restrict__ bq, const float* __restrict__ bk,
                     const float* __restrict__ bv,
                     float* __restrict__ Qf, float* __restrict__ Kf,
                     __half* __restrict__ Vh)
{
    extern __shared__ char smc[];
    const uint32_t ub = smem_u32(smc);

    const int which = blockIdx.x >> 3;
    const int n0 = (blockIdx.x & 7) * 128;
    const int m0 = blockIdx.y * 128;

    const __half* Wh = (which == 0) ? Wqh : (which == 1) ? Wkh : Wvh;
    const float* bias = (which == 0) ? bq : (which == 1) ? bk : bv;

    float acc[4][4][4];
    gemm_mainloop(xh + (size_t)m0 * 1024, Wh + (size_t)n0 * 1024, ub, acc);

    const int tid = threadIdx.x, lane = tid & 31, wid = tid >> 5;
    const int g = lane >> 2, t = lane & 3;
    const int wm = wid >> 2, wn = wid & 3;
    const float osc = (which == 0) ? 0.125f : 1.0f;

    #pragma unroll
    for (int mt = 0; mt < 4; mt++) {
        const int r0 = m0 + wm * 64 + mt * 16 + g;
        #pragma unroll
        for (int nt = 0; nt < 4; nt++) {
            const int c = n0 + wn * 32 + nt * 8 + 2 * t;
            const float2 bv2 = *(const float2*)(bias + c);
            const float o00 = acc[mt][nt][0] + bv2.x, o01 = acc[mt][nt][1] + bv2.y;
            const float o10 = acc[mt][nt][2] + bv2.x, o11 = acc[mt][nt][3] + bv2.y;
            const int h = c >> 6, d = c & 63;
            const int bb0 = r0 >> 11, tt0 = r0 & (Tn - 1);
            const int r1 = r0 + 8;
            const int bb1 = r1 >> 11, tt1 = r1 & (Tn - 1);
            const size_t p0 = ((size_t)(bb0 * Hn + h) * Tn + tt0) * Dhn + d;
            const size_t p1 = ((size_t)(bb1 * Hn + h) * Tn + tt1) * Dhn + d;
            if (which == 2) {
                *(uint32_t*)(Vh + p0) = pkh2(o00, o01);
                *(uint32_t*)(Vh + p1) = pkh2(o10, o11);
            } else {
                float* C = (which == 0) ? Qf : Kf;
                *(float2*)(C + p0) = make_float2(o00 * osc, o01 * osc);
                *(float2*)(C + p1) = make_float2(o10 * osc, o11 * osc);
            }
        }
    }
}

// ===========================================================================
// O projection: out[m,n] = attn[m,:] x Wo[n,:] + bo, fp32 row-major.
// ===========================================================================
__global__ __launch_bounds__(256)
void gemm_o_kernel(const __half* __restrict__ A, const __half* __restrict__ Wh,
                   const float* __restrict__ bias, float* __restrict__ out)
{
    extern __shared__ char smc[];
    const uint32_t ub = smem_u32(smc);

    const int n0 = blockIdx.x * 128;
    const int m0 = blockIdx.y * 128;

    float acc[4][4][4];
    gemm_mainloop(A + (size_t)m0 * 1024, Wh + (size_t)n0 * 1024, ub, acc);

    const int tid = threadIdx.x, lane = tid & 31, wid = tid >> 5;
    const int g = lane >> 2, t = lane & 3;
    const int wm = wid >> 2, wn = wid & 3;

    #pragma unroll
    for (int mt = 0; mt < 4; mt++) {
        const int r0 = m0 + wm * 64 + mt * 16 + g;
        #pragma unroll
        for (int nt = 0; nt < 4; nt++) {
            const int c = n0 + wn * 32 + nt * 8 + 2 * t;
            const float2 bv2 = *(const float2*)(bias + c);
            *(float2*)(out + (size_t)r0 * Dn + c) =
                make_float2(acc[mt][nt][0] + bv2.x, acc[mt][nt][1] + bv2.y);
            *(float2*)(out + (size_t)(r0 + 8) * Dn + c) =
                make_float2(acc[mt][nt][2] + bv2.x, acc[mt][nt][3] + bv2.y);
        }
    }
}

// ---------------------------------------------------------------------------
// RoPE: read fp32 Qf/Kf, rotate in fp32, write fp16 (single rounding).
// ---------------------------------------------------------------------------
__global__ void rope_h_kernel(const float* __restrict__ Qf, const float* __restrict__ Kf,
                              __half* __restrict__ Qh, __half* __restrict__ Kh)
{
    const int idx = blockIdx.x * blockDim.x + threadIdx.x;
    const int total = Bn * Hn * Tn * 32;
    if (idx >= total) return;

    const int i  = idx & 31;
    const int t  = (idx >> 5) & (Tn - 1);
    const int bh = idx >> 16;

    const float invf = 1.0f / powf(10000.0f, (float)i * (1.0f / 32.0f));
    const float ang  = (float)t * invf;
    float sn, cs;
    sincosf(ang, &sn, &cs);

    const size_t base = ((size_t)bh * Tn + t) * Dhn + i;

    const float q1 = Qf[base], q2 = Qf[base + 32];
    Qh[base]      = __float2half_rn(q1 * cs - q2 * sn);
    Qh[base + 32] = __float2half_rn(q2 * cs + q1 * sn);

    const float k1 = Kf[base], k2 = Kf[base + 32];
    Kh[base]      = __float2half_rn(k1 * cs - k2 * sn);
    Kh[base + 32] = __float2half_rn(k2 * cs + k1 * sn);
}

// ===========================================================================
// Flash attention, fp16 mma + cp.async double-buffered K/V.
//   CTA: 128 queries, 256 thr (8 warps x 16 q). Row stride 144B.
//   smem: Q(18432) | K0 | K1 | V0 | V1 (each 9216) = 55296 bytes.
// ===========================================================================
namespace { constexpr int ATTN_SMEM2 = 18432 + 4 * 9216; }

__global__ __launch_bounds__(256)
void attn_h_kernel(const __half* __restrict__ Q, const __half* __restrict__ K,
                   const __half* __restrict__ V, __half* __restrict__ O)
{
    extern __shared__ char asmc[];
    const uint32_t ub = smem_u32(asmc);

    const int tid  = threadIdx.x;
    const int lane = tid & 31;
    const int wid  = tid >> 5;                 // 0..7
    const int g = lane >> 2, t = lane & 3;
    const int lm   = lane & 15;
    const int lh16 = (lane >> 4) << 4;

    const int qt = blockIdx.x, bh = blockIdx.y;
    const int b = bh >> 4, h = bh & 15;

    const char* Qg = (const char*)(Q + (size_t)bh * Tn * 64 + (size_t)qt * 128 * 64);
    const char* Kg = (const char*)(K + (size_t)bh * Tn * 64);
    const char* Vg = (const char*)(V + (size_t)bh * Tn * 64);

    const uint32_t uQ = ub;
    const uint32_t uK[2] = { ub + 18432,          ub + 18432 + 9216 };
    const uint32_t uV[2] = { ub + 18432 + 2*9216, ub + 18432 + 3*9216 };

    // prologue: Q (16KB: row per 2 thr) + K/V tile0 (8KB each: row per 4 thr)
    {
        const int qrow = tid >> 1, qhf = tid & 1;
        const uint32_t qd = uQ + qrow * 144 + qhf * 64;
        const char* qs = Qg + qrow * 128 + qhf * 64;
        CP_ASYNC16(qd,      qs);
        CP_ASYNC16(qd + 16, qs + 16);
        CP_ASYNC16(qd + 32, qs + 32);
        CP_ASYNC16(qd + 48, qs + 48);
        const int kr = tid >> 2, ko = (tid & 3) * 32;
        CP_ASYNC16(uK[0] + kr * 144 + ko,      Kg + kr * 128 + ko);
        CP_ASYNC16(uK[0] + kr * 144 + ko + 16, Kg + kr * 128 + ko + 16);
        CP_ASYNC16(uV[0] + kr * 144 + ko,      Vg + kr * 128 + ko);
        CP_ASYNC16(uV[0] + kr * 144 + ko + 16, Vg + kr * 128 + ko + 16);
    }
    CP_COMMIT();
    CP_WAIT(0);
    __syncthreads();

    // Q fragments (Q already scaled by 1/8)
    uint32_t qf[4][4];
    #pragma unroll
    for (int kb = 0; kb < 4; kb++)
        ldsm4(qf[kb], uQ + (wid*16 + lm) * 144 + kb*32 + lh16);

    float ao[8][4];
    #pragma unroll
    for (int d = 0; d < 8; d++)
        #pragma unroll
        for (int e = 0; e < 4; e++) ao[d][e] = 0.f;
    float m0v = -1e30f, m1v = -1e30f, l0 = 0.f, l1 = 0.f;

    const int kr = tid >> 2, ko = (tid & 3) * 32;

    for (int i = 0; i < 32; i++) {
        if (i + 1 < 32) {
            const int s = (i + 1) & 1;
            const char* Kn = Kg + (size_t)(i + 1) * 8192;
            const char* Vn = Vg + (size_t)(i + 1) * 8192;
            CP_ASYNC16(uK[s] + kr * 144 + ko,      Kn + kr * 128 + ko);
            CP_ASYNC16(uK[s] + kr * 144 + ko + 16, Kn + kr * 128 + ko + 16);
            CP_ASYNC16(uV[s] + kr * 144 + ko,      Vn + kr * 128 + ko);
            CP_ASYNC16(uV[s] + kr * 144 + ko + 16, Vn + kr * 128 + ko + 16);
            CP_COMMIT();
            CP_WAIT(1);
        } else {
            CP_WAIT(0);
        }
        __syncthreads();

        const int s = i & 1;

        // S = Q K^T  (16q x 64k per warp)
        float sc[8][4];
        #pragma unroll
        for (int nt = 0; nt < 8; nt++)
            #pragma unroll
            for (int e = 0; e < 4; e++) sc[nt][e] = 0.f;
        #pragma unroll
        for (int nt2 = 0; nt2 < 4; nt2++) {
            #pragma unroll
            for (int kb = 0; kb < 4; kb++) {
                uint32_t bf[4];
                ldsm4(bf, uK[s] + (nt2*16 + lm) * 144 + kb*32 + lh16);
                mma16816(sc[2*nt2],     qf[kb], bf[0], bf[2]);
                mma16816(sc[2*nt2 + 1], qf[kb], bf[1], bf[3]);
            }
        }

        // online softmax (rows g / g+8, quad reduce)
        float tm0 = -1e30f, tm1 = -1e30f;
        #pragma unroll
        for (int nt = 0; nt < 8; nt++) {
            tm0 = fmaxf(tm0, fmaxf(sc[nt][0], sc[nt][1]));
            tm1 = fmaxf(tm1, fmaxf(sc[nt][2], sc[nt][3]));
        }
        tm0 = fmaxf(tm0, __shfl_xor_sync(0xffffffffu, tm0, 1));
        tm0 = fmaxf(tm0, __shfl_xor_sync(0xffffffffu, tm0, 2));
        tm1 = fmaxf(tm1, __shfl_xor_sync(0xffffffffu, tm1, 1));
        tm1 = fmaxf(tm1, __shfl_xor_sync(0xffffffffu, tm1, 2));

        const float nm0 = fmaxf(m0v, tm0), nm1 = fmaxf(m1v, tm1);
        const float es0 = __expf(m0v - nm0), es1 = __expf(m1v - nm1);
        m0v = nm0; m1v = nm1;

        float s0 = 0.f, s1 = 0.f;
        #pragma unroll
        for (int nt = 0; nt < 8; nt++) {
            sc[nt][0] = __expf(sc[nt][0] - nm0);
            sc[nt][1] = __expf(sc[nt][1] - nm0);
            sc[nt][2] = __expf(sc[nt][2] - nm1);
            sc[nt][3] = __expf(sc[nt][3] - nm1);
            s0 += sc[nt][0] + sc[nt][1];
            s1 += sc[nt][2] + sc[nt][3];
        }
        s0 += __shfl_xor_sync(0xffffffffu, s0, 1);
        s0 += __shfl_xor_sync(0xffffffffu, s0, 2);
        s1 += __shfl_xor_sync(0xffffffffu, s1, 1);
        s1 += __shfl_xor_sync(0xffffffffu, s1, 2);
        l0 = l0 * es0 + s0;
        l1 = l1 * es1 + s1;
        #pragma unroll
        for (int d = 0; d < 8; d++) {
            ao[d][0] *= es0; ao[d][1] *= es0;
            ao[d][2] *= es1; ao[d][3] *= es1;
        }

        // O += P V : P fragments straight from sc (register repack)
        #pragma unroll
        for (int kb2 = 0; kb2 < 4; kb2++) {
            uint32_t pa[4];
            pa[0] = pkh2(sc[2*kb2][0],     sc[2*kb2][1]);
            pa[1] = pkh2(sc[2*kb2][2],     sc[2*kb2][3]);
            pa[2] = pkh2(sc[2*kb2 + 1][0], sc[2*kb2 + 1][1]);
            pa[3] = pkh2(sc[2*kb2 + 1][2], sc[2*kb2 + 1][3]);
            #pragma unroll
            for (int dp = 0; dp < 4; dp++) {
                uint32_t vf[4];
                ldsm4t(vf, uV[s] + (kb2*16 + lm) * 144 + dp*32 + lh16);
                mma16816(ao[2*dp],     pa, vf[0], vf[1]);
                mma16816(ao[2*dp + 1], pa, vf[2], vf[3]);
            }
        }
        __syncthreads();   // all warps done with stage s before re-issue
    }

    const float inv0 = 1.f / l0, inv1 = 1.f / l1;
    const int r0 = qt * 128 + wid * 16 + g;
    const size_t mrow0 = (size_t)(b * Tn + r0) * Dn;
    const size_t mrow1 = (size_t)(b * Tn + r0 + 8) * Dn;
    #pragma unroll
    for (int dt = 0; dt < 8; dt++) {
        const int c = h * 64 + dt * 8 + 2 * t;
        *(uint32_t*)(O + mrow0 + c) = pkh2(ao[dt][0] * inv0, ao[dt][1] * inv0);
        *(uint32_t*)(O + mrow1 + c) = pkh2(ao[dt][2] * inv1, ao[dt][3] * inv1);
    }
}

// ---------------------------------------------------------------------------
extern "C" void kernel_launch(void* const* d_in, const int* in_sizes, int n_in,
                              void* d_out, int out_size)
{
    (void)in_sizes; (void)n_in; (void)out_size;
    const float* x  = (const float*)d_in[0];
    const float* Wq = (const float*)d_in[1];
    const float* bq = (const float*)d_in[2];
    const float* Wk = (const float*)d_in[3];
    const float* bk = (const float*)d_in[4];
    const float* Wv = (const float*)d_in[5];
    const float* bv = (const float*)d_in[6];
    const float* Wo = (const float*)d_in[7];
    const float* bo = (const float*)d_in[8];
    float* out = (float*)d_out;

    __half *xh, *Wqh, *Wkh, *Wvh, *Woh, *Qh, *Kh, *Vh, *attn;
    float *Qf, *Kf;
    cudaGetSymbolAddress((void**)&xh,   g_xh);
    cudaGetSymbolAddress((void**)&Wqh,  g_Wqh);
    cudaGetSymbolAddress((void**)&Wkh,  g_Wkh);
    cudaGetSymbolAddress((void**)&Wvh,  g_Wvh);
    cudaGetSymbolAddress((void**)&Woh,  g_Woh);
    cudaGetSymbolAddress((void**)&Qf,   g_Qf);
    cudaGetSymbolAddress((void**)&Kf,   g_Kf);
    cudaGetSymbolAddress((void**)&Qh,   g_Qh);
    cudaGetSymbolAddress((void**)&Kh,   g_Kh);
    cudaGetSymbolAddress((void**)&Vh,   g_Vh);
    cudaGetSymbolAddress((void**)&attn, g_attn);

    cudaFuncSetAttribute(gemm_qkv_kernel, cudaFuncAttributeMaxDynamicSharedMemorySize, GSMEM);
    cudaFuncSetAttribute(gemm_o_kernel,   cudaFuncAttributeMaxDynamicSharedMemorySize, GSMEM);
    cudaFuncSetAttribute(attn_h_kernel,   cudaFuncAttributeMaxDynamicSharedMemorySize, ATTN_SMEM2);

    // fp32 -> fp16 pre-conversion
    const int xn4 = Mn * Dn / 4, wn4 = Dn * Dn / 4;
    cvt_h_kernel<<<(xn4 + 255) / 256, 256>>>(x,  xh,  xn4);
    cvt_h_kernel<<<(wn4 + 255) / 256, 256>>>(Wq, Wqh, wn4);
    cvt_h_kernel<<<(wn4 + 255) / 256, 256>>>(Wk, Wkh, wn4);
    cvt_h_kernel<<<(wn4 + 255) / 256, 256>>>(Wv, Wvh, wn4);
    cvt_h_kernel<<<(wn4 + 255) / 256, 256>>>(Wo, Woh, wn4);

    gemm_qkv_kernel<<<dim3(24, 32), 256, GSMEM>>>(xh, Wqh, Wkh, Wvh,
                                                  bq, bk, bv, Qf, Kf, Vh);

    const int rope_total = Bn * Hn * Tn * 32;
    rope_h_kernel<<<(rope_total + 255) / 256, 256>>>(Qf, Kf, Qh, Kh);

    attn_h_kernel<<<dim3(Tn / 128, Bn * Hn), 256, ATTN_SMEM2>>>(Qh, Kh, Vh, attn);

    gemm_o_kernel<<<dim3(8, 32), 256, GSMEM>>>(attn, Woh, bo, out);
}

// round 11
// speedup vs baseline: 6.8986x; 1.0502x over previous
#include <cuda_runtime.h>
#include <cuda_fp16.h>
#include <math.h>
#include <cstdint>

// ---------------------------------------------------------------------------
// RoPE MHA on GB300 (sm_103 family-generic target).
// R11: RoPE fused into QKV epilogue (warp tile 32x64 so rotation partners
//      are thread-local); single fused fp32->fp16 convert; attention with
//      3-stage cp.async ring + exp2-domain softmax.
// ---------------------------------------------------------------------------

namespace {
constexpr int Bn=2, Tn=2048, Hn=16, Dhn=64, Dn=1024, Mn=4096;
constexpr float QSC = 0.125f * 1.44269504088896340736f;   // 1/sqrt(64) * log2(e)
}

__device__ __half g_xh[(size_t)Mn*Dn];
__device__ __half g_Wqh[(size_t)Dn*Dn];
__device__ __half g_Wkh[(size_t)Dn*Dn];
__device__ __half g_Wvh[(size_t)Dn*Dn];
__device__ __half g_Woh[(size_t)Dn*Dn];
__device__ __half g_Qh[(size_t)Mn*Dn];
__device__ __half g_Kh[(size_t)Mn*Dn];
__device__ __half g_Vh[(size_t)Mn*Dn];
__device__ __half g_attn[(size_t)Mn*Dn];
__device__ float2 g_tbl[(size_t)Tn*32];        // (cos, sin) per (t, i)

// ----------------------------- helpers ------------------------------------
__device__ __forceinline__ uint32_t smem_u32(const void* p) {
    uint32_t a;
    asm("{ .reg .u64 t; cvta.to.shared.u64 t, %1; cvt.u32.u64 %0, t; }"
        : "=r"(a) : "l"(p));
    return a;
}
__device__ __forceinline__ uint32_t pkh2(float lo, float hi) {
    __half2 h = __floats2half2_rn(lo, hi);
    return *reinterpret_cast<uint32_t*>(&h);
}
__device__ __forceinline__ float ex2f(float x) {
    float r;
    asm("ex2.approx.f32 %0, %1;" : "=f"(r) : "f"(x));
    return r;
}
__device__ __forceinline__ void mma16816(float* c, const uint32_t* a,
                                         uint32_t b0, uint32_t b1) {
    asm volatile(
        "mma.sync.aligned.m16n8k16.row.col.f32.f16.f16.f32 "
        "{%0,%1,%2,%3},{%4,%5,%6,%7},{%8,%9},{%0,%1,%2,%3};"
        : "+f"(c[0]), "+f"(c[1]), "+f"(c[2]), "+f"(c[3])
        : "r"(a[0]), "r"(a[1]), "r"(a[2]), "r"(a[3]), "r"(b0), "r"(b1));
}
__device__ __forceinline__ void ldsm4(uint32_t* r, uint32_t addr) {
    asm volatile("ldmatrix.sync.aligned.m8n8.x4.shared.b16 {%0,%1,%2,%3}, [%4];"
        : "=r"(r[0]), "=r"(r[1]), "=r"(r[2]), "=r"(r[3]) : "r"(addr));
}
__device__ __forceinline__ void ldsm4t(uint32_t* r, uint32_t addr) {
    asm volatile("ldmatrix.sync.aligned.m8n8.x4.trans.shared.b16 {%0,%1,%2,%3}, [%4];"
        : "=r"(r[0]), "=r"(r[1]), "=r"(r[2]), "=r"(r[3]) : "r"(addr));
}
#define CP_ASYNC16(dst, src) \
    asm volatile("cp.async.cg.shared.global [%0], [%1], 16;" :: "r"(dst), "l"(src))
#define CP_COMMIT() asm volatile("cp.async.commit_group;" ::: "memory")
#define CP_WAIT(n)  asm volatile("cp.async.wait_group %0;" :: "n"(n) : "memory")

// ---------------------------------------------------------------------------
// Fused fp32 -> fp16 conversion of x, Wq, Wk, Wv, Wo (single launch).
// ---------------------------------------------------------------------------
namespace { constexpr int XN4 = Mn*Dn/4, WN4 = Dn*Dn/4; }

__global__ void cvt_all_kernel(const float* __restrict__ x,
                               const float* __restrict__ Wq, const float* __restrict__ Wk,
                               const float* __restrict__ Wv, const float* __restrict__ Wo)
{
    const int i = blockIdx.x * blockDim.x + threadIdx.x;
    const float* src; __half* dst; int off;
    if (i < XN4)            { src = x;  dst = g_xh;  off = i; }
    else {
        const int j = i - XN4, sel = j / WN4; off = j % WN4;
        src = (sel == 0) ? Wq : (sel == 1) ? Wk : (sel == 2) ? Wv : Wo;
        dst = (sel == 0) ? g_Wqh : (sel == 1) ? g_Wkh : (sel == 2) ? g_Wvh : g_Woh;
    }
    const float4 v = ((const float4*)src)[off];
    uint2 o;
    o.x = pkh2(v.x, v.y);
    o.y = pkh2(v.z, v.w);
    ((uint2*)dst)[off] = o;
}

// ---------------------------------------------------------------------------
// RoPE cos/sin table: tbl[t*32+i] = (cos(t*w_i), sin(t*w_i))
// ---------------------------------------------------------------------------
__global__ void rope_tbl_kernel()
{
    const int idx = blockIdx.x * blockDim.x + threadIdx.x;
    if (idx >= Tn * 32) return;
    const int i = idx & 31, t = idx >> 5;
    const float invf = 1.0f / powf(10000.0f, (float)i * (1.0f / 32.0f));
    float sn, cs;
    sincosf((float)t * invf, &sn, &cs);
    g_tbl[idx] = make_float2(cs, sn);
}

// ===========================================================================
// GEMM mainloop: 128x128 tile, 8 warps as 4m x 2n (32 rows x 64 cols each),
//   3-stage cp.async, K-chunk 64, 144B smem row stride.
// ===========================================================================
namespace {
constexpr int STGB  = 18432;
constexpr int GSMEM = 6 * STGB;
constexpr int NIT   = 16;
}

__device__ __forceinline__ void gload64(uint32_t dst, const __half* src,
                                        int row, int hf, int k0)
{
    const char* s = (const char*)(src + (size_t)row * 1024 + k0 + hf * 32);
    const uint32_t d = dst + row * 144 + hf * 64;
    CP_ASYNC16(d,      s);
    CP_ASYNC16(d + 16, s + 16);
    CP_ASYNC16(d + 32, s + 32);
    CP_ASYNC16(d + 48, s + 48);
}

__device__ __forceinline__ void gemm_mainloop(const __half* Ag, const __half* Wg,
                                              uint32_t ub, float (&acc)[2][8][4])
{
    const int tid  = threadIdx.x;
    const int lane = tid & 31;
    const int wid  = tid >> 5;
    const int lm   = lane & 15;
    const int lh16 = (lane >> 4) << 4;
    const int wm = wid & 3, wn = wid >> 2;
    const int row = tid >> 1, hf = tid & 1;

    #pragma unroll
    for (int i = 0; i < 2; i++)
        #pragma unroll
        for (int j = 0; j < 8; j++)
            #pragma unroll
            for (int e = 0; e < 4; e++) acc[i][j][e] = 0.f;

    gload64(ub,            Ag, row, hf, 0);
    gload64(ub + 3 * STGB, Wg, row, hf, 0);
    CP_COMMIT();
    gload64(ub + STGB,            Ag, row, hf, 64);
    gload64(ub + 3 * STGB + STGB, Wg, row, hf, 64);
    CP_COMMIT();

    for (int i = 0; i < NIT; i++) {
        CP_WAIT(1);
        __syncthreads();
        if (i + 2 < NIT) {
            const int s = (i + 2) % 3;
            gload64(ub + s * STGB,       Ag, row, hf, (i + 2) * 64);
            gload64(ub + (3 + s) * STGB, Wg, row, hf, (i + 2) * 64);
        }
        CP_COMMIT();

        const uint32_t uA = ub + (i % 3) * STGB;
        const uint32_t uW = ub + (3 + i % 3) * STGB;
        #pragma unroll
        for (int kb = 0; kb < 4; kb++) {
            uint32_t af[2][4];
            #pragma unroll
            for (int mt = 0; mt < 2; mt++)
                ldsm4(af[mt], uA + (wm*32 + mt*16 + lm) * 144 + kb*32 + lh16);
            uint32_t bf[4][4];
            #pragma unroll
            for (int p = 0; p < 4; p++)
                ldsm4(bf[p], uW + (wn*64 + p*16 + lm) * 144 + kb*32 + lh16);
            #pragma unroll
            for (int mt = 0; mt < 2; mt++)
                #pragma unroll
                for (int nt = 0; nt < 8; nt++) {
                    const int p = nt >> 1, q = nt & 1;
                    mma16816(acc[mt][nt], af[mt], bf[p][q], bf[p][2 + q]);
                }
        }
    }
}

// ===========================================================================
// Fused QKV projection + RoPE epilogue. grid (24, 32): which = bx/8.
//   Q -> g_Qh fp16, rope + *QSC ; K -> g_Kh fp16, rope ; V -> g_Vh fp16.
//   Each warp's 64 output columns = exactly one head; rotation partners
//   (d, d+32) live at acc[.][nt] / acc[.][nt+4] in the SAME thread.
// ===========================================================================
__global__ __launch_bounds__(256)
void gemm_qkv_kernel(const float* __restrict__ bq, const float* __restrict__ bk,
                     const float* __restrict__ bv)
{
    extern __shared__ char smc[];
    const uint32_t ub = smem_u32(smc);

    const int which = blockIdx.x >> 3;
    const int n0 = (blockIdx.x & 7) * 128;
    const int m0 = blockIdx.y * 128;

    const __half* Wh = (which == 0) ? g_Wqh : (which == 1) ? g_Wkh : g_Wvh;
    const float* bias = (which == 0) ? bq : (which == 1) ? bk : bv;

    float acc[2][8][4];
    gemm_mainloop(g_xh + (size_t)m0 * 1024, Wh + (size_t)n0 * 1024, ub, acc);

    const int tid = threadIdx.x, lane = tid & 31, wid = tid >> 5;
    const int g = lane >> 2, t = lane & 3;
    const int wm = wid & 3, wn = wid >> 2;

    const int hcol = n0 + wn * 64;       // head-aligned column base
    const int h    = hcol >> 6;

    if (which == 2) {
        // V: plain bias + fp16 scatter
        #pragma unroll
        for (int mt = 0; mt < 2; mt++) {
            const int r0 = m0 + wm * 32 + mt * 16 + g;
            const int bb = r0 >> 11, tt0 = r0 & (Tn - 1);
            const size_t b0 = ((size_t)(bb * Hn + h) * Tn + tt0) * Dhn;
            const size_t b1 = b0 + 8 * Dhn;
            #pragma unroll
            for (int nt = 0; nt < 8; nt++) {
                const int d = nt * 8 + 2 * t;
                const float2 bv2 = *(const float2*)(bias + hcol + d);
                *(uint32_t*)(g_Vh + b0 + d) = pkh2(acc[mt][nt][0] + bv2.x, acc[mt][nt][1] + bv2.y);
                *(uint32_t*)(g_Vh + b1 + d) = pkh2(acc[mt][nt][2] + bv2.x, acc[mt][nt][3] + bv2.y);
            }
        }
    } else {
        __half* C = (which == 0) ? g_Qh : g_Kh;
        const float sc = (which == 0) ? QSC : 1.0f;
        #pragma unroll
        for (int mt = 0; mt < 2; mt++) {
            const int r0 = m0 + wm * 32 + mt * 16 + g;
            const int bb = r0 >> 11, tt0 = r0 & (Tn - 1), tt1 = tt0 + 8;
            const size_t b0 = ((size_t)(bb * Hn + h) * Tn + tt0) * Dhn;
            const size_t b1 = b0 + 8 * Dhn;
            #pragma unroll
            for (int nt = 0; nt < 4; nt++) {
                const int i0 = nt * 8 + 2 * t;           // d in [0,32)
                const float2 bl = *(const float2*)(bias + hcol + i0);
                const float2 bh = *(const float2*)(bias + hcol + i0 + 32);
                // (cos,sin) for (tt0,i0),(tt0,i0+1),(tt1,i0),(tt1,i0+1)
                const float4 ca = *(const float4*)(&g_tbl[(size_t)tt0 * 32 + i0]);
                const float4 cb = *(const float4*)(&g_tbl[(size_t)tt1 * 32 + i0]);
                // token tt0 (elements 0,1)
                {
                    const float xl0 = acc[mt][nt][0] + bl.x, xl1 = acc[mt][nt][1] + bl.y;
                    const float xh0 = acc[mt][nt+4][0] + bh.x, xh1 = acc[mt][nt+4][1] + bh.y;
                    const float lo0 = (xl0 * ca.x - xh0 * ca.y) * sc;
                    const float lo1 = (xl1 * ca.z - xh1 * ca.w) * sc;
                    const float hi0 = (xh0 * ca.x + xl0 * ca.y) * sc;
                    const float hi1 = (xh1 * ca.z + xl1 * ca.w) * sc;
                    *(uint32_t*)(C + b0 + i0)      = pkh2(lo0, lo1);
                    *(uint32_t*)(C + b0 + i0 + 32) = pkh2(hi0, hi1);
                }
                // token tt1 (elements 2,3)
                {
                    const float xl0 = acc[mt][nt][2] + bl.x, xl1 = acc[mt][nt][3] + bl.y;
                    const float xh0 = acc[mt][nt+4][2] + bh.x, xh1 = acc[mt][nt+4][3] + bh.y;
                    const float lo0 = (xl0 * cb.x - xh0 * cb.y) * sc;
                    const float lo1 = (xl1 * cb.z - xh1 * cb.w) * sc;
                    const float hi0 = (xh0 * cb.x + xl0 * cb.y) * sc;
                    const float hi1 = (xh1 * cb.z + xl1 * cb.w) * sc;
                    *(uint32_t*)(C + b1 + i0)      = pkh2(lo0, lo1);
                    *(uint32_t*)(C + b1 + i0 + 32) = pkh2(hi0, hi1);
                }
            }
        }
    }
}

// ===========================================================================
// O projection: out[m,n] = attn[m,:] x Wo[n,:] + bo, fp32 row-major.
// ===========================================================================
__global__ __launch_bounds__(256)
void gemm_o_kernel(const float* __restrict__ bias, float* __restrict__ out)
{
    extern __shared__ char smc[];
    const uint32_t ub = smem_u32(smc);

    const int n0 = blockIdx.x * 128;
    const int m0 = blockIdx.y * 128;

    float acc[2][8][4];
    gemm_mainloop(g_attn + (size_t)m0 * 1024, g_Woh + (size_t)n0 * 1024, ub, acc);

    const int tid = threadIdx.x, lane = tid & 31, wid = tid >> 5;
    const int g = lane >> 2, t = lane & 3;
    const int wm = wid & 3, wn = wid >> 2;

    #pragma unroll
    for (int mt = 0; mt < 2; mt++) {
        const int r0 = m0 + wm * 32 + mt * 16 + g;
        #pragma unroll
        for (int nt = 0; nt < 8; nt++) {
            const int c = n0 + wn * 64 + nt * 8 + 2 * t;
            const float2 bv2 = *(const float2*)(bias + c);
            *(float2*)(out + (size_t)r0 * Dn + c) =
                make_float2(acc[mt][nt][0] + bv2.x, acc[mt][nt][1] + bv2.y);
            *(float2*)(out + (size_t)(r0 + 8) * Dn + c) =
                make_float2(acc[mt][nt][2] + bv2.x, acc[mt][nt][3] + bv2.y);
        }
    }
}

// ===========================================================================
// Flash attention: 128q/CTA, 256 thr, 3-stage cp.async K/V ring (1 sync/iter),
// exp2-domain softmax (log2e folded into stored Q).
//   smem: Q(18432) | K0,K1,K2 | V0,V1,V2 (each 9216) = 73728 bytes.
// ===========================================================================
namespace { constexpr int ATTN_SMEM3 = 18432 + 6 * 9216; }

__global__ __launch_bounds__(256)
void attn_h_kernel(const __half* __restrict__ Q, const __half* __restrict__ K,
                   const __half* __restrict__ V, __half* __restrict__ O)
{
    extern __shared__ char asmc[];
    const uint32_t ub = smem_u32(asmc);

    const int tid  = threadIdx.x;
    const int lane = tid & 31;
    const int wid  = tid >> 5;
    const int g = lane >> 2, t = lane & 3;
    const int lm   = lane & 15;
    const int lh16 = (lane >> 4) << 4;

    const int qt = blockIdx.x, bh = blockIdx.y;
    const int b = bh >> 4, h = bh & 15;

    const char* Qg = (const char*)(Q + (size_t)bh * Tn * 64 + (size_t)qt * 128 * 64);
    const char* Kg = (const char*)(K + (size_t)bh * Tn * 64);
    const char* Vg = (const char*)(V + (size_t)bh * Tn * 64);

    const uint32_t uQ = ub;
    uint32_t uK[3], uV[3];
    #pragma unroll
    for (int s = 0; s < 3; s++) {
        uK[s] = ub + 18432 + s * 9216;
        uV[s] = ub + 18432 + (3 + s) * 9216;
    }

    const int kr = tid >> 2, ko = (tid & 3) * 32;

    // prologue: Q + K/V tiles 0 and 1 (two commit groups)
    {
        const int qrow = tid >> 1, qhf = tid & 1;
        const uint32_t qd = uQ + qrow * 144 + qhf * 64;
        const char* qs = Qg + qrow * 128 + qhf * 64;
        CP_ASYNC16(qd,      qs);
        CP_ASYNC16(qd + 16, qs + 16);
        CP_ASYNC16(qd + 32, qs + 32);
        CP_ASYNC16(qd + 48, qs + 48);
        CP_ASYNC16(uK[0] + kr * 144 + ko,      Kg + kr * 128 + ko);
        CP_ASYNC16(uK[0] + kr * 144 + ko + 16, Kg + kr * 128 + ko + 16);
        CP_ASYNC16(uV[0] + kr * 144 + ko,      Vg + kr * 128 + ko);
        CP_ASYNC16(uV[0] + kr * 144 + ko + 16, Vg + kr * 128 + ko + 16);
        CP_COMMIT();
        CP_ASYNC16(uK[1] + kr * 144 + ko,      Kg + 8192 + kr * 128 + ko);
        CP_ASYNC16(uK[1] + kr * 144 + ko + 16, Kg + 8192 + kr * 128 + ko + 16);
        CP_ASYNC16(uV[1] + kr * 144 + ko,      Vg + 8192 + kr * 128 + ko);
        CP_ASYNC16(uV[1] + kr * 144 + ko + 16, Vg + 8192 + kr * 128 + ko + 16);
        CP_COMMIT();
    }

    CP_WAIT(1);
    __syncthreads();

    // Q fragments (pre-scaled by 0.125*log2e in the QKV epilogue)
    uint32_t qf[4][4];
    #pragma unroll
    for (int kb = 0; kb < 4; kb++)
        ldsm4(qf[kb], uQ + (wid*16 + lm) * 144 + kb*32 + lh16);

    float ao[8][4];
    #pragma unroll
    for (int d = 0; d < 8; d++)
        #pragma unroll
        for (int e = 0; e < 4; e++) ao[d][e] = 0.f;
    float m0v = -1e30f, m1v = -1e30f, l0 = 0.f, l1 = 0.f;

    for (int i = 0; i < 32; i++) {
        if (i > 0) {             // tile i completeness (tile 0 waited above)
            CP_WAIT(1);
            __syncthreads();
        }
        if (i + 2 < 32) {
            const int s = (i + 2) % 3;
            const char* Kn = Kg + (size_t)(i + 2) * 8192;
            const char* Vn = Vg + (size_t)(i + 2) * 8192;
            CP_ASYNC16(uK[s] + kr * 144 + ko,      Kn + kr * 128 + ko);
            CP_ASYNC16(uK[s] + kr * 144 + ko + 16, Kn + kr * 128 + ko + 16);
            CP_ASYNC16(uV[s] + kr * 144 + ko,      Vn + kr * 128 + ko);
            CP_ASYNC16(uV[s] + kr * 144 + ko + 16, Vn + kr * 128 + ko + 16);
        }
        CP_COMMIT();

        const int s = i % 3;

        // S = Q K^T  (16q x 64k per warp), log2 domain
        float sc[8][4];
        #pragma unroll
        for (int nt = 0; nt < 8; nt++)
            #pragma unroll
            for (int e = 0; e < 4; e++) sc[nt][e] = 0.f;
        #pragma unroll
        for (int nt2 = 0; nt2 < 4; nt2++) {
            #pragma unroll
            for (int kb = 0; kb < 4; kb++) {
                uint32_t bf[4];
                ldsm4(bf, uK[s] + (nt2*16 + lm) * 144 + kb*32 + lh16);
                mma16816(sc[2*nt2],     qf[kb], bf[0], bf[2]);
                mma16816(sc[2*nt2 + 1], qf[kb], bf[1], bf[3]);
            }
        }

        // online softmax (base-2), rows g / g+8, quad reduce
        float tm0 = -1e30f, tm1 = -1e30f;
        #pragma unroll
        for (int nt = 0; nt < 8; nt++) {
            tm0 = fmaxf(tm0, fmaxf(sc[nt][0], sc[nt][1]));
            tm1 = fmaxf(tm1, fmaxf(sc[nt][2], sc[nt][3]));
        }
        tm0 = fmaxf(tm0, __shfl_xor_sync(0xffffffffu, tm0, 1));
        tm0 = fmaxf(tm0, __shfl_xor_sync(0xffffffffu, tm0, 2));
        tm1 = fmaxf(tm1, __shfl_xor_sync(0xffffffffu, tm1, 1));
        tm1 = fmaxf(tm1, __shfl_xor_sync(0xffffffffu, tm1, 2));

        const float nm0 = fmaxf(m0v, tm0), nm1 = fmaxf(m1v, tm1);
        const float es0 = ex2f(m0v - nm0), es1 = ex2f(m1v - nm1);
        m0v = nm0; m1v = nm1;

        float s0 = 0.f, s1 = 0.f;
        #pragma unroll
        for (int nt = 0; nt < 8; nt++) {
            sc[nt][0] = ex2f(sc[nt][0] - nm0);
            sc[nt][1] = ex2f(sc[nt][1] - nm0);
            sc[nt][2] = ex2f(sc[nt][2] - nm1);
            sc[nt][3] = ex2f(sc[nt][3] - nm1);
            s0 += sc[nt][0] + sc[nt][1];
            s1 += sc[nt][2] + sc[nt][3];
        }
        s0 += __shfl_xor_sync(0xffffffffu, s0, 1);
        s0 += __shfl_xor_sync(0xffffffffu, s0, 2);
        s1 += __shfl_xor_sync(0xffffffffu, s1, 1);
        s1 += __shfl_xor_sync(0xffffffffu, s1, 2);
        l0 = l0 * es0 + s0;
        l1 = l1 * es1 + s1;
        #pragma unroll
        for (int d = 0; d < 8; d++) {
            ao[d][0] *= es0; ao[d][1] *= es0;
            ao[d][2] *= es1; ao[d][3] *= es1;
        }

        // O += P V (register repack of sc -> A fragments)
        #pragma unroll
        for (int kb2 = 0; kb2 < 4; kb2++) {
            uint32_t pa[4];
            pa[0] = pkh2(sc[2*kb2][0],     sc[2*kb2][1]);
            pa[1] = pkh2(sc[2*kb2][2],     sc[2*kb2][3]);
            pa[2] = pkh2(sc[2*kb2 + 1][0], sc[2*kb2 + 1][1]);
            pa[3] = pkh2(sc[2*kb2 + 1][2], sc[2*kb2 + 1][3]);
            #pragma unroll
            for (int dp = 0; dp < 4; dp++) {
                uint32_t vf[4];
                ldsm4t(vf, uV[s] + (kb2*16 + lm) * 144 + dp*32 + lh16);
                mma16816(ao[2*dp],     pa, vf[0], vf[1]);
                mma16816(ao[2*dp + 1], pa, vf[2], vf[3]);
            }
        }
    }

    const float inv0 = 1.f / l0, inv1 = 1.f / l1;
    const int r0 = qt * 128 + wid * 16 + g;
    const size_t mrow0 = (size_t)(b * Tn + r0) * Dn;
    const size_t mrow1 = (size_t)(b * Tn + r0 + 8) * Dn;
    #pragma unroll
    for (int dt = 0; dt < 8; dt++) {
        const int c = h * 64 + dt * 8 + 2 * t;
        *(uint32_t*)(O + mrow0 + c) = pkh2(ao[dt][0] * inv0, ao[dt][1] * inv0);
        *(uint32_t*)(O + mrow1 + c) = pkh2(ao[dt][2] * inv1, ao[dt][3] * inv1);
    }
}

// ---------------------------------------------------------------------------
extern "C" void kernel_launch(void* const* d_in, const int* in_sizes, int n_in,
                              void* d_out, int out_size)
{
    (void)in_sizes; (void)n_in; (void)out_size;
    const float* x  = (const float*)d_in[0];
    const float* Wq = (const float*)d_in[1];
    const float* bq = (const float*)d_in[2];
    const float* Wk = (const float*)d_in[3];
    const float* bk = (const float*)d_in[4];
    const float* Wv = (const float*)d_in[5];
    const float* bv = (const float*)d_in[6];
    const float* Wo = (const float*)d_in[7];
    const float* bo = (const float*)d_in[8];
    float* out = (float*)d_out;

    __half *Qh, *Kh, *Vh, *attn;
    cudaGetSymbolAddress((void**)&Qh,   g_Qh);
    cudaGetSymbolAddress((void**)&Kh,   g_Kh);
    cudaGetSymbolAddress((void**)&Vh,   g_Vh);
    cudaGetSymbolAddress((void**)&attn, g_attn);

    cudaFuncSetAttribute(gemm_qkv_kernel, cudaFuncAttributeMaxDynamicSharedMemorySize, GSMEM);
    cudaFuncSetAttribute(gemm_o_kernel,   cudaFuncAttributeMaxDynamicSharedMemorySize, GSMEM);
    cudaFuncSetAttribute(attn_h_kernel,   cudaFuncAttributeMaxDynamicSharedMemorySize, ATTN_SMEM3);

    const int cvt_total = XN4 + 4 * WN4;                   // 2,097,152 float4s
    cvt_all_kernel<<<(cvt_total + 255) / 256, 256>>>(x, Wq, Wk, Wv, Wo);
    rope_tbl_kernel<<<(Tn * 32 + 255) / 256, 256>>>();

    gemm_qkv_kernel<<<dim3(24, 32), 256, GSMEM>>>(bq, bk, bv);

    attn_h_kernel<<<dim3(Tn / 128, Bn * Hn), 256, ATTN_SMEM3>>>(Qh, Kh, Vh, attn);

    gemm_o_kernel<<<dim3(8, 32), 256, GSMEM>>>(bo, out);
}